// round 11
// baseline (speedup 1.0000x reference)
#include <cuda_runtime.h>
#include <cuda_bf16.h>
#include <cstdint>

// ---------------------------------------------------------------------------
// MambaLayer (bidirectional VideoMamba), B200 sm_100 — round 11
// (round-10 source resubmitted after broker infra failure)
// conv fused into xproj GEMM staging; residual+LN2 fused into out_proj epilogue
// ---------------------------------------------------------------------------

#define BB   4
#define DM   128
#define LL   8192
#define DI   256
#define NS   16
#define DTR  8
#define NDBL 40
#define MTOK (BB*LL)
#define CHUNK 64
#define NCH  (LL/CHUNK)
#define OUT_SMEM 73728

// ------------------------- scratch (static device mem) ---------------------
__device__ __nv_bfloat16  g_xnh   [MTOK*DM];
__device__ __nv_bfloat16  g_xnl   [MTOK*DM];
__device__ float          g_xz    [MTOK*2*DI];
__device__ float          g_dbl   [2][MTOK*NDBL];
__device__ uint32_t       g_xc32  [2][MTOK*DI];     // packed bf16 (hi | lo<<16)
__device__ float          g_ydir  [2][MTOK*DI];
__device__ float          g_hend  [2*NCH*BB*NS*DI];
__device__ float          g_P     [2*NCH*BB*NS*DI];
__device__ float          g_hinit [2*NCH*BB*NS*DI];
__device__ __nv_bfloat16  g_wih[512*128],  g_wil[512*128];
__device__ __nv_bfloat16  g_woh[128*256],  g_wol[128*256];
__device__ __nv_bfloat16  g_xpwh[2][64*256], g_xpwl[2][64*256]; // rows>=40 zero

// ------------------------- math helpers -------------------------------------
__device__ __forceinline__ float siluf(float x) {
    return __fdividef(x, 1.f + __expf(-x));
}
__device__ __forceinline__ void mkpow(float r, float* w) {
    float r2 = r * r, r3 = r2 * r, r4 = r2 * r2;
    float r5 = r4 * r, r6 = r4 * r2, r7 = r4 * r3, r8 = r4 * r4;
    w[0]=r;  w[1]=r2; w[2]=r3; w[3]=r4; w[4]=r5; w[5]=r6; w[6]=r7; w[7]=r8;
    w[8]=r8*r; w[9]=r8*r2; w[10]=r8*r3; w[11]=r8*r4;
    w[12]=r8*r5; w[13]=r8*r6; w[14]=r8*r7; w[15]=r8*r8;
}
__device__ __forceinline__ void bsplit(float v, __nv_bfloat16& hi, __nv_bfloat16& lo) {
    hi = __float2bfloat16(v);
    lo = __float2bfloat16(v - __bfloat162float(hi));
}
__device__ __forceinline__ uint32_t pack2(__nv_bfloat16 a, __nv_bfloat16 b) {
    return (uint32_t)__bfloat16_as_ushort(a) | ((uint32_t)__bfloat16_as_ushort(b) << 16);
}
__device__ __forceinline__ float unpack_sum(uint32_t p) {
    __nv_bfloat16 h = __ushort_as_bfloat16((unsigned short)(p & 0xffffu));
    __nv_bfloat16 l = __ushort_as_bfloat16((unsigned short)(p >> 16));
    return __bfloat162float(h) + __bfloat162float(l);
}
__device__ __forceinline__ void dt_math(float a, float& r, float& dt) {
    float e = __expf(a);
    r = __fdividef(1.f, 1.f + e);
    if (a > 15.f)      dt = a;
    else if (a > -3.f) dt = __logf(1.f + e);
    else               dt = e * fmaf(e, fmaf(e, 0.33333334f, -0.5f), 1.f);
}
__device__ __forceinline__ void mma16816(float* c, const uint32_t* a, const uint32_t* b) {
    asm volatile(
        "mma.sync.aligned.m16n8k16.row.col.f32.bf16.bf16.f32 "
        "{%0,%1,%2,%3}, {%4,%5,%6,%7}, {%8,%9}, {%0,%1,%2,%3};"
        : "+f"(c[0]), "+f"(c[1]), "+f"(c[2]), "+f"(c[3])
        : "r"(a[0]), "r"(a[1]), "r"(a[2]), "r"(a[3]), "r"(b[0]), "r"(b[1]));
}

// ------------------------- weight convert -----------------------------------
__global__ void k_wconv(const float* __restrict__ wi, const float* __restrict__ wo,
                        const float* __restrict__ xpf, const float* __restrict__ xpb) {
    int i = blockIdx.x * 256 + threadIdx.x;
    if (i < 512 * 128) { bsplit(wi[i], g_wih[i], g_wil[i]); return; }
    int j = i - 512 * 128;
    if (j < 128 * 256) { bsplit(wo[j], g_woh[j], g_wol[j]); return; }
    int k = j - 128 * 256;
    if (k < 2 * 64 * 256) {
        int dir = k / (64 * 256);
        int idx = k - dir * 64 * 256;
        int n = idx >> 8;
        const float* src = dir ? xpb : xpf;
        float v = (n < NDBL) ? src[idx] : 0.f;
        bsplit(v, g_xpwh[dir][idx], g_xpwl[dir][idx]);
    }
}

// ------------------------- LN1 + transpose + bf16 split ---------------------
__global__ void k_ln1(const float* __restrict__ x,
                      const float* __restrict__ w, const float* __restrict__ bia) {
    __shared__ float s[DM][65];
    __shared__ float rs_[4][64], rq_[4][64];
    __shared__ float mu[64], rstd[64];
    int tid = threadIdx.x;
    int m0 = blockIdx.x * 64;
    int b  = m0 / LL;
    int l0 = m0 % LL;
#pragma unroll
    for (int i = 0; i < 32; i++) {
        int e = tid + i * 256;
        int l = e & 63, c = e >> 6;
        s[c][l] = x[(b * DM + c) * LL + l0 + l];
    }
    __syncthreads();
    {
        int tok = tid & 63, part = tid >> 6;
        float su = 0.f, sq = 0.f;
#pragma unroll
        for (int cc = 0; cc < 32; cc++) {
            float v = s[part * 32 + cc][tok];
            su += v; sq = fmaf(v, v, sq);
        }
        rs_[part][tok] = su; rq_[part][tok] = sq;
    }
    __syncthreads();
    if (tid < 64) {
        float su = rs_[0][tid] + rs_[1][tid] + rs_[2][tid] + rs_[3][tid];
        float sq = rq_[0][tid] + rq_[1][tid] + rq_[2][tid] + rq_[3][tid];
        float m = su * (1.f / DM);
        float var = sq * (1.f / DM) - m * m;
        mu[tid] = m; rstd[tid] = rsqrtf(var + 1e-5f);
    }
    __syncthreads();
#pragma unroll
    for (int i = 0; i < 32; i++) {
        int e = tid + i * 256;
        int c = e & 127, l = e >> 7;
        float v = s[c][l];
        int gi = (m0 + l) * DM + c;
        float vn = (v - mu[l]) * rstd[l] * w[c] + bia[c];
        bsplit(vn, g_xnh[gi], g_xnl[gi]);
    }
}

// ------------------------- in_proj GEMM (bf16 hi/lo A) ----------------------
__global__ __launch_bounds__(256) void gemm_in(
        const __nv_bfloat16* __restrict__ Ah, const __nv_bfloat16* __restrict__ Al,
        float* __restrict__ C) {
    __shared__ uint32_t As[2][128][18];
    __shared__ uint32_t Bs[2][128][18];
    const int tid = threadIdx.x;
    const int m0 = blockIdx.x * 128, n0 = blockIdx.y * 128;
    const int wid = tid >> 5, lane = tid & 31;
    const int wm0 = (wid & 1) * 64, wn0 = (wid >> 1) * 32;
    const int gr = lane >> 2, cp = lane & 3;
    float acc[4][4][4] = {};
    const int lrow = tid >> 1, lhalf = tid & 1;
    for (int k0 = 0; k0 < DM; k0 += 32) {
#pragma unroll
        for (int sel = 0; sel < 2; sel++) {
            const __nv_bfloat16* src = sel ? Al : Ah;
            const uint4* gp = (const uint4*)&src[(size_t)(m0 + lrow) * DM + k0 + lhalf * 16];
            uint4 v0 = gp[0], v1 = gp[1];
            uint32_t* d = &As[sel][lrow][lhalf * 8];
            d[0] = v0.x; d[1] = v0.y; d[2] = v0.z; d[3] = v0.w;
            d[4] = v1.x; d[5] = v1.y; d[6] = v1.z; d[7] = v1.w;
        }
#pragma unroll
        for (int sel = 0; sel < 2; sel++) {
            const __nv_bfloat16* src = sel ? g_wil : g_wih;
            const uint4* gp = (const uint4*)&src[(size_t)(n0 + lrow) * DM + k0 + lhalf * 16];
            uint4 v0 = gp[0], v1 = gp[1];
            uint32_t* d = &Bs[sel][lrow][lhalf * 8];
            d[0] = v0.x; d[1] = v0.y; d[2] = v0.z; d[3] = v0.w;
            d[4] = v1.x; d[5] = v1.y; d[6] = v1.z; d[7] = v1.w;
        }
        __syncthreads();
#pragma unroll
        for (int pass = 0; pass < 3; pass++) {
            uint32_t (*pA)[18] = As[pass == 2 ? 1 : 0];
            uint32_t (*pB)[18] = Bs[pass == 1 ? 1 : 0];
#pragma unroll
            for (int k16 = 0; k16 < 2; k16++) {
                const int kp = k16 * 8;
                uint32_t a[4][4], bf[4][2];
#pragma unroll
                for (int i = 0; i < 4; i++) {
                    int rbase = wm0 + 16 * i;
                    a[i][0] = pA[rbase + gr][kp + cp];
                    a[i][1] = pA[rbase + gr + 8][kp + cp];
                    a[i][2] = pA[rbase + gr][kp + cp + 4];
                    a[i][3] = pA[rbase + gr + 8][kp + cp + 4];
                }
#pragma unroll
                for (int j = 0; j < 4; j++) {
                    int brow = wn0 + 8 * j + gr;
                    bf[j][0] = pB[brow][kp + cp];
                    bf[j][1] = pB[brow][kp + cp + 4];
                }
#pragma unroll
                for (int i = 0; i < 4; i++)
#pragma unroll
                    for (int j = 0; j < 4; j++)
                        mma16816(acc[i][j], a[i], bf[j]);
            }
        }
        __syncthreads();
    }
#pragma unroll
    for (int i = 0; i < 4; i++) {
#pragma unroll
        for (int j = 0; j < 4; j++) {
            int row = m0 + wm0 + 16 * i + gr;
            int col = n0 + wn0 + 8 * j + cp * 2;
            *(float2*)&C[(size_t)row * 512 + col] = make_float2(acc[i][j][0], acc[i][j][1]);
            *(float2*)&C[(size_t)(row + 8) * 512 + col] = make_float2(acc[i][j][2], acc[i][j][3]);
        }
    }
}

// ------------------------- x_proj GEMM with fused conv+silu -----------------
// A[m][c] = silu(conv_dir(xz_xi)[m][c]) computed in staging; writes g_xc32 too.
__global__ __launch_bounds__(256) void gemm_xproj(
        const float* __restrict__ cwf, const float* __restrict__ cbf,
        const float* __restrict__ cwb, const float* __restrict__ cbb,
        float* __restrict__ Cbase) {
    __shared__ uint32_t As[2][128][18];
    __shared__ uint32_t Bs[2][64][18];
    const int tid = threadIdx.x;
    const int dir = blockIdx.y;
    const int m0 = blockIdx.x * 128;
    const int b  = m0 >> 13;
    const int s0 = m0 & (LL - 1);
    const __nv_bfloat16* Bh = g_xpwh[dir];
    const __nv_bfloat16* Bl = g_xpwl[dir];
    const float* cw = dir ? cwb : cwf;
    const float* cb = dir ? cbb : cbf;
    float* C = Cbase + (size_t)dir * MTOK * NDBL;
    uint32_t* xcout = g_xc32[dir];
    const int wid = tid >> 5, lane = tid & 31;
    const int wm0 = (wid & 3) * 32, wn0 = (wid >> 2) * 32;
    const int gr = lane >> 2, cp = lane & 3;
    float acc[2][4][4] = {};
    const int lrow = tid >> 1, lhalf = tid & 1;
    const int m = m0 + lrow;
    const int s = s0 + lrow;
    int tt[4]; bool tv[4];
#pragma unroll
    for (int j = 0; j < 4; j++) {
        tt[j] = dir ? (LL + 2 - s - j) : (s - 3 + j);
        tv[j] = (tt[j] >= 0) && (tt[j] < LL);
    }
    const float* xrow[4];
#pragma unroll
    for (int j = 0; j < 4; j++)
        xrow[j] = g_xz + (size_t)(b * LL + (tv[j] ? tt[j] : 0)) * 512;

    for (int k0 = 0; k0 < DI; k0 += 32) {
        const int c0 = k0 + lhalf * 16;
#pragma unroll
        for (int g = 0; g < 4; g++) {
            int cg = c0 + g * 4;
            float4 t[4];
#pragma unroll
            for (int j = 0; j < 4; j++)
                t[j] = tv[j] ? *(const float4*)&xrow[j][cg] : make_float4(0.f, 0.f, 0.f, 0.f);
            float4 cbv = *(const float4*)&cb[cg];
            float cv[4];
#pragma unroll
            for (int i = 0; i < 4; i++) {
                float4 wv = *(const float4*)&cw[(cg + i) * 4];
                float ti0 = (i==0)?t[0].x:(i==1)?t[0].y:(i==2)?t[0].z:t[0].w;
                float ti1 = (i==0)?t[1].x:(i==1)?t[1].y:(i==2)?t[1].z:t[1].w;
                float ti2 = (i==0)?t[2].x:(i==1)?t[2].y:(i==2)?t[2].z:t[2].w;
                float ti3 = (i==0)?t[3].x:(i==1)?t[3].y:(i==2)?t[3].z:t[3].w;
                float bi  = (i==0)?cbv.x:(i==1)?cbv.y:(i==2)?cbv.z:cbv.w;
                float a = bi;
                a = fmaf(wv.x, ti0, a); a = fmaf(wv.y, ti1, a);
                a = fmaf(wv.z, ti2, a); a = fmaf(wv.w, ti3, a);
                cv[i] = siluf(a);
            }
            __nv_bfloat16 h[4], l[4];
#pragma unroll
            for (int i = 0; i < 4; i++) bsplit(cv[i], h[i], l[i]);
            As[0][lrow][lhalf * 8 + g * 2 + 0] = pack2(h[0], h[1]);
            As[0][lrow][lhalf * 8 + g * 2 + 1] = pack2(h[2], h[3]);
            As[1][lrow][lhalf * 8 + g * 2 + 0] = pack2(l[0], l[1]);
            As[1][lrow][lhalf * 8 + g * 2 + 1] = pack2(l[2], l[3]);
            uint4 pk;
            pk.x = pack2(h[0], l[0]); pk.y = pack2(h[1], l[1]);
            pk.z = pack2(h[2], l[2]); pk.w = pack2(h[3], l[3]);
            *(uint4*)&xcout[(size_t)m * DI + cg] = pk;
        }
        if (tid < 128) {
#pragma unroll
            for (int sel = 0; sel < 2; sel++) {
                const __nv_bfloat16* src = sel ? Bl : Bh;
                const uint4* gp = (const uint4*)&src[(size_t)lrow * DI + k0 + lhalf * 16];
                uint4 v0 = gp[0], v1 = gp[1];
                uint32_t* d = &Bs[sel][lrow][lhalf * 8];
                d[0] = v0.x; d[1] = v0.y; d[2] = v0.z; d[3] = v0.w;
                d[4] = v1.x; d[5] = v1.y; d[6] = v1.z; d[7] = v1.w;
            }
        }
        __syncthreads();
#pragma unroll
        for (int pass = 0; pass < 3; pass++) {
            uint32_t (*pA)[18] = As[pass == 2 ? 1 : 0];
            uint32_t (*pB)[18] = Bs[pass == 1 ? 1 : 0];
#pragma unroll
            for (int k16 = 0; k16 < 2; k16++) {
                const int kp = k16 * 8;
                uint32_t a[2][4], bf[4][2];
#pragma unroll
                for (int i = 0; i < 2; i++) {
                    int rbase = wm0 + 16 * i;
                    a[i][0] = pA[rbase + gr][kp + cp];
                    a[i][1] = pA[rbase + gr + 8][kp + cp];
                    a[i][2] = pA[rbase + gr][kp + cp + 4];
                    a[i][3] = pA[rbase + gr + 8][kp + cp + 4];
                }
#pragma unroll
                for (int j = 0; j < 4; j++) {
                    int brow = wn0 + 8 * j + gr;
                    bf[j][0] = pB[brow][kp + cp];
                    bf[j][1] = pB[brow][kp + cp + 4];
                }
#pragma unroll
                for (int i = 0; i < 2; i++)
#pragma unroll
                    for (int j = 0; j < 4; j++)
                        mma16816(acc[i][j], a[i], bf[j]);
            }
        }
        __syncthreads();
    }
#pragma unroll
    for (int i = 0; i < 2; i++) {
#pragma unroll
        for (int j = 0; j < 4; j++) {
            int row = m0 + wm0 + 16 * i + gr;
            int col = wn0 + 8 * j + cp * 2;
            if (col < NDBL) {
                *(float2*)&C[(size_t)row * NDBL + col] = make_float2(acc[i][j][0], acc[i][j][1]);
                *(float2*)&C[(size_t)(row + 8) * NDBL + col] = make_float2(acc[i][j][2], acc[i][j][3]);
            }
        }
    }
}

// ------------------------- out_proj GEMM + residual + LN2 -------------------
// Dynamic smem (73728 B): GEMM buffers, then reused for epilogue LN.
__global__ __launch_bounds__(256) void gemm_out(
        const float* __restrict__ x,
        const float* __restrict__ lw, const float* __restrict__ lb,
        float* __restrict__ out) {
    extern __shared__ __align__(16) char smraw[];
    uint32_t (*As)[128][18] = (uint32_t (*)[128][18])smraw;
    uint32_t (*Bs)[128][18] = (uint32_t (*)[128][18])(smraw + 36864);
    const int tid = threadIdx.x;
    const int m0 = blockIdx.x * 128;
    const int wid = tid >> 5, lane = tid & 31;
    const int wm0 = (wid & 1) * 64, wn0 = (wid >> 1) * 32;
    const int gr = lane >> 2, cp = lane & 3;
    float acc[4][4][4] = {};
    const int lrow = tid >> 1, lhalf = tid & 1;
    const float* Yf = g_ydir[0];
    const float* Yb = g_ydir[1];
    for (int k0 = 0; k0 < DI; k0 += 32) {
        {
            const float4* pf = (const float4*)&Yf[(size_t)(m0 + lrow) * DI + k0 + lhalf * 16];
            const float4* pb = (const float4*)&Yb[(size_t)(m0 + lrow) * DI + k0 + lhalf * 16];
            float v[16];
#pragma unroll
            for (int q = 0; q < 4; q++) {
                float4 a = pf[q], bq = pb[q];
                v[q*4+0] = a.x + bq.x; v[q*4+1] = a.y + bq.y;
                v[q*4+2] = a.z + bq.z; v[q*4+3] = a.w + bq.w;
            }
            uint32_t* dh = &As[0][lrow][lhalf * 8];
            uint32_t* dl = &As[1][lrow][lhalf * 8];
#pragma unroll
            for (int q = 0; q < 8; q++) {
                __nv_bfloat16 h0, l0, h1, l1;
                bsplit(v[2*q], h0, l0);
                bsplit(v[2*q+1], h1, l1);
                dh[q] = pack2(h0, h1);
                dl[q] = pack2(l0, l1);
            }
        }
#pragma unroll
        for (int sel = 0; sel < 2; sel++) {
            const __nv_bfloat16* src = sel ? g_wol : g_woh;
            const uint4* gp = (const uint4*)&src[(size_t)lrow * DI + k0 + lhalf * 16];
            uint4 v0 = gp[0], v1 = gp[1];
            uint32_t* d = &Bs[sel][lrow][lhalf * 8];
            d[0] = v0.x; d[1] = v0.y; d[2] = v0.z; d[3] = v0.w;
            d[4] = v1.x; d[5] = v1.y; d[6] = v1.z; d[7] = v1.w;
        }
        __syncthreads();
#pragma unroll
        for (int pass = 0; pass < 3; pass++) {
            uint32_t (*pA)[18] = As[pass == 2 ? 1 : 0];
            uint32_t (*pB)[18] = Bs[pass == 1 ? 1 : 0];
#pragma unroll
            for (int k16 = 0; k16 < 2; k16++) {
                const int kp = k16 * 8;
                uint32_t a[4][4], bf[4][2];
#pragma unroll
                for (int i = 0; i < 4; i++) {
                    int rbase = wm0 + 16 * i;
                    a[i][0] = pA[rbase + gr][kp + cp];
                    a[i][1] = pA[rbase + gr + 8][kp + cp];
                    a[i][2] = pA[rbase + gr][kp + cp + 4];
                    a[i][3] = pA[rbase + gr + 8][kp + cp + 4];
                }
#pragma unroll
                for (int j = 0; j < 4; j++) {
                    int brow = wn0 + 8 * j + gr;
                    bf[j][0] = pB[brow][kp + cp];
                    bf[j][1] = pB[brow][kp + cp + 4];
                }
#pragma unroll
                for (int i = 0; i < 4; i++)
#pragma unroll
                    for (int j = 0; j < 4; j++)
                        mma16816(acc[i][j], a[i], bf[j]);
            }
        }
        __syncthreads();
    }
    // ---- epilogue: acc -> smem, + residual, LN over channels, write out ----
    float (*sD)[129] = (float (*)[129])smraw;
    float (*prs)[2] = (float (*)[2])(smraw + 66048);
    float (*prq)[2] = (float (*)[2])(smraw + 67072);
    float* mu   = (float*)(smraw + 68096);
    float* rstd = (float*)(smraw + 68608);
#pragma unroll
    for (int i = 0; i < 4; i++) {
#pragma unroll
        for (int j = 0; j < 4; j++) {
            int row = wm0 + 16 * i + gr;
            int col = wn0 + 8 * j + cp * 2;
            sD[row][col]     = acc[i][j][0];
            sD[row][col + 1] = acc[i][j][1];
            sD[row + 8][col]     = acc[i][j][2];
            sD[row + 8][col + 1] = acc[i][j][3];
        }
    }
    __syncthreads();
    const int b  = m0 / LL;
    const int l0 = m0 % LL;
#pragma unroll
    for (int i = 0; i < 64; i++) {
        int e = tid + i * 256;
        int l = e & 127, c = e >> 7;
        sD[l][c] += x[(size_t)(b * DM + c) * LL + l0 + l];
    }
    __syncthreads();
    {
        int r = tid >> 1, half = tid & 1;
        float su = 0.f, sq = 0.f;
#pragma unroll
        for (int cc = 0; cc < 64; cc++) {
            float v = sD[r][half * 64 + cc];
            su += v; sq = fmaf(v, v, sq);
        }
        prs[r][half] = su; prq[r][half] = sq;
    }
    __syncthreads();
    if (tid < 128) {
        float su = prs[tid][0] + prs[tid][1];
        float sq = prq[tid][0] + prq[tid][1];
        float m = su * (1.f / DM);
        float var = sq * (1.f / DM) - m * m;
        mu[tid] = m; rstd[tid] = rsqrtf(var + 1e-5f);
    }
    __syncthreads();
#pragma unroll
    for (int i = 0; i < 64; i++) {
        int e = tid + i * 256;
        int l = e & 127, c = e >> 7;
        out[(size_t)(b * DM + c) * LL + l0 + l] =
            (sD[l][c] - mu[l]) * rstd[l] * lw[c] + lb[c];
    }
}

// ------------------------- scan pass 1 (inline dt) --------------------------
__global__ void k_scan1(const float* __restrict__ Alog_f, const float* __restrict__ Alog_b,
                        const float* __restrict__ dtw_f, const float* __restrict__ dtb_f,
                        const float* __restrict__ dtw_b, const float* __restrict__ dtb_b) {
    int ch = blockIdx.x, b = blockIdx.y, dir = blockIdx.z, d = threadIdx.x;
    const float* Alog = dir ? Alog_b : Alog_f;
    const float* dtw  = dir ? dtw_b : dtw_f;
    float dtb = (dir ? dtb_b : dtb_f)[d];
    __shared__ __align__(16) float sd[CHUNK][24];
    int t0 = ch * CHUNK;
    const float* gsrc = g_dbl[dir] + (size_t)(b * LL + t0) * NDBL;
    for (int i = threadIdx.x; i < CHUNK * 6; i += 256) {
        int t = i / 6, q = i - t * 6;
        *((float4*)&sd[t][q * 4]) = *((const float4*)&gsrc[t * NDBL + q * 4]);
    }
    float Ad[NS], h[NS], wdt[DTR];
    bool fast = true;
#pragma unroll
    for (int n = 0; n < NS; n++) {
        Ad[n] = -__expf(Alog[d * NS + n]);
        fast = fast && (fabsf(Ad[n] + (float)(n + 1)) <= 1e-5f * (n + 1));
    }
#pragma unroll
    for (int i = 0; i < DTR; i++) wdt[i] = dtw[d * DTR + i];
#pragma unroll
    for (int n = 0; n < NS; n++) h[n] = 0.f;
    const uint32_t* xc = g_xc32[dir] + (size_t)(b * LL + t0) * DI + d;
    float rP = 1.f, S = 0.f;
    __syncthreads();
    if (fast) {
#pragma unroll 2
        for (int t = 0; t < CHUNK; t++) {
            const float* row = sd[t];
            float4 d0 = *(const float4*)&row[0];
            float4 d1 = *(const float4*)&row[4];
            float a = dtb;
            a = fmaf(wdt[0], d0.x, a); a = fmaf(wdt[1], d0.y, a);
            a = fmaf(wdt[2], d0.z, a); a = fmaf(wdt[3], d0.w, a);
            a = fmaf(wdt[4], d1.x, a); a = fmaf(wdt[5], d1.y, a);
            a = fmaf(wdt[6], d1.z, a); a = fmaf(wdt[7], d1.w, a);
            float r, dt; dt_math(a, r, dt);
            float cB = dt * unpack_sum(xc[(size_t)t * DI]);
            float4 B0 = *(const float4*)&row[8],  B1 = *(const float4*)&row[12];
            float4 B2 = *(const float4*)&row[16], B3 = *(const float4*)&row[20];
            float Bv[16] = {B0.x,B0.y,B0.z,B0.w, B1.x,B1.y,B1.z,B1.w,
                            B2.x,B2.y,B2.z,B2.w, B3.x,B3.y,B3.z,B3.w};
            float wv[NS];
            mkpow(r, wv);
            rP *= r;
#pragma unroll
            for (int n = 0; n < NS; n++)
                h[n] = fmaf(wv[n], h[n], cB * Bv[n]);
        }
    } else {
        for (int t = 0; t < CHUNK; t++) {
            const float* row = sd[t];
            float a = dtb;
#pragma unroll
            for (int i = 0; i < DTR; i++) a = fmaf(wdt[i], row[i], a);
            float r, dt; dt_math(a, r, dt);
            float cB = dt * unpack_sum(xc[(size_t)t * DI]);
            S += dt;
#pragma unroll
            for (int n = 0; n < NS; n++)
                h[n] = fmaf(__expf(dt * Ad[n]), h[n], cB * row[8 + n]);
        }
    }
    int base = ((dir * NCH + ch) * BB + b) * NS;
    if (fast) {
        float pw[NS];
        mkpow(rP, pw);
#pragma unroll
        for (int n = 0; n < NS; n++) {
            g_hend[(base + n) * DI + d] = h[n];
            g_P[(base + n) * DI + d]    = pw[n];
        }
    } else {
#pragma unroll
        for (int n = 0; n < NS; n++) {
            g_hend[(base + n) * DI + d] = h[n];
            g_P[(base + n) * DI + d]    = __expf(Ad[n] * S);
        }
    }
}

// ------------------------- scan pass 2 --------------------------------------
__global__ void k_scan2() {
    int d = threadIdx.x;
    int n   = blockIdx.x & 15;
    int b   = (blockIdx.x >> 4) & 3;
    int dir = blockIdx.x >> 6;
    float hs = 0.f;
    for (int ch = 0; ch < NCH; ch++) {
        int idx = (((dir * NCH + ch) * BB + b) * NS + n) * DI + d;
        g_hinit[idx] = hs;
        hs = fmaf(g_P[idx], hs, g_hend[idx]);
    }
}

// ------------------------- scan pass 3 (inline dt, emit y) ------------------
__global__ void k_scan3(const float* __restrict__ Alog_f, const float* __restrict__ Dsk_f,
                        const float* __restrict__ Alog_b, const float* __restrict__ Dsk_b,
                        const float* __restrict__ dtw_f, const float* __restrict__ dtb_f,
                        const float* __restrict__ dtw_b, const float* __restrict__ dtb_b) {
    int ch = blockIdx.x, b = blockIdx.y, dir = blockIdx.z, d = threadIdx.x;
    const float* Alog = dir ? Alog_b : Alog_f;
    const float* dtw  = dir ? dtw_b : dtw_f;
    float dtb = (dir ? dtb_b : dtb_f)[d];
    float Dd  = (dir ? Dsk_b : Dsk_f)[d];
    __shared__ __align__(16) float sd[CHUNK][40];
    int t0 = ch * CHUNK;
    const float* gsrc = g_dbl[dir] + (size_t)(b * LL + t0) * NDBL;
    for (int i = threadIdx.x; i < CHUNK * 10; i += 256) {
        int t = i / 10, q = i - t * 10;
        *((float4*)&sd[t][q * 4]) = *((const float4*)&gsrc[t * NDBL + q * 4]);
    }
    float Ad[NS], h[NS], wdt[DTR];
    bool fast = true;
#pragma unroll
    for (int n = 0; n < NS; n++) {
        Ad[n] = -__expf(Alog[d * NS + n]);
        fast = fast && (fabsf(Ad[n] + (float)(n + 1)) <= 1e-5f * (n + 1));
    }
#pragma unroll
    for (int i = 0; i < DTR; i++) wdt[i] = dtw[d * DTR + i];
    int base = ((dir * NCH + ch) * BB + b) * NS;
#pragma unroll
    for (int n = 0; n < NS; n++) h[n] = g_hinit[(base + n) * DI + d];
    const uint32_t* xc = g_xc32[dir] + (size_t)(b * LL + t0) * DI + d;
    const float* xzz = g_xz + (size_t)b * LL * 512 + DI + d;
    float* yout = g_ydir[dir] + (size_t)b * LL * DI + d;
    __syncthreads();
    if (fast) {
#pragma unroll 2
        for (int t = 0; t < CHUNK; t++) {
            const float* row = sd[t];
            float4 d0 = *(const float4*)&row[0];
            float4 d1 = *(const float4*)&row[4];
            float a = dtb;
            a = fmaf(wdt[0], d0.x, a); a = fmaf(wdt[1], d0.y, a);
            a = fmaf(wdt[2], d0.z, a); a = fmaf(wdt[3], d0.w, a);
            a = fmaf(wdt[4], d1.x, a); a = fmaf(wdt[5], d1.y, a);
            a = fmaf(wdt[6], d1.z, a); a = fmaf(wdt[7], d1.w, a);
            float r, dt; dt_math(a, r, dt);
            float xv = unpack_sum(xc[(size_t)t * DI]);
            float cB = dt * xv;
            float4 B0 = *(const float4*)&row[8],  B1 = *(const float4*)&row[12];
            float4 B2 = *(const float4*)&row[16], B3 = *(const float4*)&row[20];
            float4 C0 = *(const float4*)&row[24], C1 = *(const float4*)&row[28];
            float4 C2 = *(const float4*)&row[32], C3 = *(const float4*)&row[36];
            float Bv[16] = {B0.x,B0.y,B0.z,B0.w, B1.x,B1.y,B1.z,B1.w,
                            B2.x,B2.y,B2.z,B2.w, B3.x,B3.y,B3.z,B3.w};
            float Cv[16] = {C0.x,C0.y,C0.z,C0.w, C1.x,C1.y,C1.z,C1.w,
                            C2.x,C2.y,C2.z,C2.w, C3.x,C3.y,C3.z,C3.w};
            float wv[NS];
            mkpow(r, wv);
            float y = 0.f;
#pragma unroll
            for (int n = 0; n < NS; n++) {
                h[n] = fmaf(wv[n], h[n], cB * Bv[n]);
                y = fmaf(h[n], Cv[n], y);
            }
            int torig = dir ? (LL - 1 - (t0 + t)) : (t0 + t);
            float zv = xzz[(size_t)torig * 512];
            yout[(size_t)torig * DI] = (y + xv * Dd) * siluf(zv);
        }
    } else {
        for (int t = 0; t < CHUNK; t++) {
            const float* row = sd[t];
            float a = dtb;
#pragma unroll
            for (int i = 0; i < DTR; i++) a = fmaf(wdt[i], row[i], a);
            float r, dt; dt_math(a, r, dt);
            float xv = unpack_sum(xc[(size_t)t * DI]);
            float cB = dt * xv;
            float y = 0.f;
#pragma unroll
            for (int n = 0; n < NS; n++) {
                h[n] = fmaf(__expf(dt * Ad[n]), h[n], cB * row[8 + n]);
                y = fmaf(h[n], row[24 + n], y);
            }
            int torig = dir ? (LL - 1 - (t0 + t)) : (t0 + t);
            float zv = xzz[(size_t)torig * 512];
            yout[(size_t)torig * DI] = (y + xv * Dd) * siluf(zv);
        }
    }
}

// ------------------------- launch ------------------------------------------
extern "C" void kernel_launch(void* const* d_in, const int* in_sizes, int n_in,
                              void* d_out, int out_size) {
    const float* x        = (const float*)d_in[0];
    const float* ln1_w    = (const float*)d_in[1];
    const float* ln1_b    = (const float*)d_in[2];
    const float* ln2_w    = (const float*)d_in[3];
    const float* ln2_b    = (const float*)d_in[4];
    const float* in_proj  = (const float*)d_in[5];
    const float* out_proj = (const float*)d_in[6];
    const float* conv_w_f = (const float*)d_in[7];
    const float* conv_b_f = (const float*)d_in[8];
    const float* xproj_f  = (const float*)d_in[9];
    const float* dtw_f    = (const float*)d_in[10];
    const float* dtb_f    = (const float*)d_in[11];
    const float* Alog_f   = (const float*)d_in[12];
    const float* D_f      = (const float*)d_in[13];
    const float* conv_w_b = (const float*)d_in[14];
    const float* conv_b_b = (const float*)d_in[15];
    const float* xproj_b  = (const float*)d_in[16];
    const float* dtw_b    = (const float*)d_in[17];
    const float* dtb_b    = (const float*)d_in[18];
    const float* Alog_b   = (const float*)d_in[19];
    const float* D_b      = (const float*)d_in[20];
    float* out = (float*)d_out;

    static bool attr_done = false;
    if (!attr_done) {
        cudaFuncSetAttribute(gemm_out, cudaFuncAttributeMaxDynamicSharedMemorySize, OUT_SMEM);
        attr_done = true;
    }

    float *p_xz, *p_dbl;
    __nv_bfloat16 *p_xnh, *p_xnl;
    cudaGetSymbolAddress((void**)&p_xz,  g_xz);
    cudaGetSymbolAddress((void**)&p_dbl, g_dbl);
    cudaGetSymbolAddress((void**)&p_xnh, g_xnh);
    cudaGetSymbolAddress((void**)&p_xnl, g_xnl);

    // 0. weight bf16 splits
    int wtot = 512 * 128 + 128 * 256 + 2 * 64 * 256;
    k_wconv<<<(wtot + 255) / 256, 256>>>(in_proj, out_proj, xproj_f, xproj_b);

    // 1. LN1 + transpose + split
    k_ln1<<<MTOK / 64, 256>>>(x, ln1_w, ln1_b);

    // 2. in_proj: [32768,128] x [512,128]^T -> g_xz
    gemm_in<<<dim3(MTOK / 128, 4), 256>>>(p_xnh, p_xnl, p_xz);

    // 3. x_proj with fused conv+silu (writes g_dbl and g_xc32), both dirs
    gemm_xproj<<<dim3(MTOK / 128, 2), 256>>>(conv_w_f, conv_b_f, conv_w_b, conv_b_b,
                                             p_dbl);

    // 4-6. chunked selective scan (dt inline)
    k_scan1<<<dim3(NCH, BB, 2), 256>>>(Alog_f, Alog_b, dtw_f, dtb_f, dtw_b, dtb_b);
    k_scan2<<<2 * BB * NS, 256>>>();
    k_scan3<<<dim3(NCH, BB, 2), 256>>>(Alog_f, D_f, Alog_b, D_b,
                                       dtw_f, dtb_f, dtw_b, dtb_b);

    // 7. out_proj + residual + LN2 -> final output
    gemm_out<<<dim3(MTOK / 128, 1), 256, OUT_SMEM>>>(x, ln2_w, ln2_b, out);
}

// round 12
// speedup vs baseline: 1.0928x; 1.0928x over previous
#include <cuda_runtime.h>
#include <cuda_bf16.h>
#include <cstdint>

// ---------------------------------------------------------------------------
// MambaLayer (bidirectional VideoMamba), B200 sm_100 — round 12
// round-8 structure + fused out_proj/residual/LN2 epilogue (conv fusion reverted)
// ---------------------------------------------------------------------------

#define BB   4
#define DM   128
#define LL   8192
#define DI   256
#define NS   16
#define DTR  8
#define NDBL 40
#define MTOK (BB*LL)
#define CHUNK 64
#define NCH  (LL/CHUNK)
#define OUT_SMEM 73728

// ------------------------- scratch (static device mem) ---------------------
__device__ __nv_bfloat16  g_xnh   [MTOK*DM];
__device__ __nv_bfloat16  g_xnl   [MTOK*DM];
__device__ float          g_xz    [MTOK*2*DI];
__device__ float          g_dbl   [2][MTOK*NDBL];
__device__ uint32_t       g_xc32  [2][MTOK*DI];     // packed bf16 (hi | lo<<16)
__device__ float          g_ydir  [2][MTOK*DI];
__device__ float          g_hend  [2*NCH*BB*NS*DI];
__device__ float          g_P     [2*NCH*BB*NS*DI];
__device__ float          g_hinit [2*NCH*BB*NS*DI];
__device__ __nv_bfloat16  g_wih[512*128],  g_wil[512*128];
__device__ __nv_bfloat16  g_woh[128*256],  g_wol[128*256];
__device__ __nv_bfloat16  g_xpwh[2][64*256], g_xpwl[2][64*256]; // rows>=40 zero

// ------------------------- math helpers -------------------------------------
__device__ __forceinline__ float siluf(float x) {
    return __fdividef(x, 1.f + __expf(-x));
}
__device__ __forceinline__ void mkpow(float r, float* w) {
    float r2 = r * r, r3 = r2 * r, r4 = r2 * r2;
    float r5 = r4 * r, r6 = r4 * r2, r7 = r4 * r3, r8 = r4 * r4;
    w[0]=r;  w[1]=r2; w[2]=r3; w[3]=r4; w[4]=r5; w[5]=r6; w[6]=r7; w[7]=r8;
    w[8]=r8*r; w[9]=r8*r2; w[10]=r8*r3; w[11]=r8*r4;
    w[12]=r8*r5; w[13]=r8*r6; w[14]=r8*r7; w[15]=r8*r8;
}
__device__ __forceinline__ void bsplit(float v, __nv_bfloat16& hi, __nv_bfloat16& lo) {
    hi = __float2bfloat16(v);
    lo = __float2bfloat16(v - __bfloat162float(hi));
}
__device__ __forceinline__ uint32_t pack2(__nv_bfloat16 a, __nv_bfloat16 b) {
    return (uint32_t)__bfloat16_as_ushort(a) | ((uint32_t)__bfloat16_as_ushort(b) << 16);
}
__device__ __forceinline__ float unpack_sum(uint32_t p) {
    __nv_bfloat16 h = __ushort_as_bfloat16((unsigned short)(p & 0xffffu));
    __nv_bfloat16 l = __ushort_as_bfloat16((unsigned short)(p >> 16));
    return __bfloat162float(h) + __bfloat162float(l);
}
__device__ __forceinline__ void dt_math(float a, float& r, float& dt) {
    float e = __expf(a);
    r = __fdividef(1.f, 1.f + e);
    if (a > 15.f)      dt = a;
    else if (a > -3.f) dt = __logf(1.f + e);
    else               dt = e * fmaf(e, fmaf(e, 0.33333334f, -0.5f), 1.f);
}
__device__ __forceinline__ void mma16816(float* c, const uint32_t* a, const uint32_t* b) {
    asm volatile(
        "mma.sync.aligned.m16n8k16.row.col.f32.bf16.bf16.f32 "
        "{%0,%1,%2,%3}, {%4,%5,%6,%7}, {%8,%9}, {%0,%1,%2,%3};"
        : "+f"(c[0]), "+f"(c[1]), "+f"(c[2]), "+f"(c[3])
        : "r"(a[0]), "r"(a[1]), "r"(a[2]), "r"(a[3]), "r"(b[0]), "r"(b[1]));
}

// ------------------------- weight convert -----------------------------------
__global__ void k_wconv(const float* __restrict__ wi, const float* __restrict__ wo,
                        const float* __restrict__ xpf, const float* __restrict__ xpb) {
    int i = blockIdx.x * 256 + threadIdx.x;
    if (i < 512 * 128) { bsplit(wi[i], g_wih[i], g_wil[i]); return; }
    int j = i - 512 * 128;
    if (j < 128 * 256) { bsplit(wo[j], g_woh[j], g_wol[j]); return; }
    int k = j - 128 * 256;
    if (k < 2 * 64 * 256) {
        int dir = k / (64 * 256);
        int idx = k - dir * 64 * 256;
        int n = idx >> 8;
        const float* src = dir ? xpb : xpf;
        float v = (n < NDBL) ? src[idx] : 0.f;
        bsplit(v, g_xpwh[dir][idx], g_xpwl[dir][idx]);
    }
}

// ------------------------- LN1 + transpose + bf16 split ---------------------
__global__ void k_ln1(const float* __restrict__ x,
                      const float* __restrict__ w, const float* __restrict__ bia) {
    __shared__ float s[DM][65];
    __shared__ float rs_[4][64], rq_[4][64];
    __shared__ float mu[64], rstd[64];
    int tid = threadIdx.x;
    int m0 = blockIdx.x * 64;
    int b  = m0 / LL;
    int l0 = m0 % LL;
#pragma unroll
    for (int i = 0; i < 32; i++) {
        int e = tid + i * 256;
        int l = e & 63, c = e >> 6;
        s[c][l] = x[(b * DM + c) * LL + l0 + l];
    }
    __syncthreads();
    {
        int tok = tid & 63, part = tid >> 6;
        float su = 0.f, sq = 0.f;
#pragma unroll
        for (int cc = 0; cc < 32; cc++) {
            float v = s[part * 32 + cc][tok];
            su += v; sq = fmaf(v, v, sq);
        }
        rs_[part][tok] = su; rq_[part][tok] = sq;
    }
    __syncthreads();
    if (tid < 64) {
        float su = rs_[0][tid] + rs_[1][tid] + rs_[2][tid] + rs_[3][tid];
        float sq = rq_[0][tid] + rq_[1][tid] + rq_[2][tid] + rq_[3][tid];
        float m = su * (1.f / DM);
        float var = sq * (1.f / DM) - m * m;
        mu[tid] = m; rstd[tid] = rsqrtf(var + 1e-5f);
    }
    __syncthreads();
#pragma unroll
    for (int i = 0; i < 32; i++) {
        int e = tid + i * 256;
        int c = e & 127, l = e >> 7;
        float v = s[c][l];
        int gi = (m0 + l) * DM + c;
        float vn = (v - mu[l]) * rstd[l] * w[c] + bia[c];
        bsplit(vn, g_xnh[gi], g_xnl[gi]);
    }
}

// ------------------------- mma.sync bf16-split GEMM -------------------------
// AMODE 0: A1/A2 bf16 hi/lo.  1: A1 packed uint32.
__device__ __forceinline__ void stage_b_tile(
        const __nv_bfloat16* Bh, const __nv_bfloat16* Bl,
        uint32_t (*Bs0)[18], uint32_t (*Bs1)[18],
        int n0, int KTOT, int k0, int lrow, int lhalf) {
#pragma unroll
    for (int sel = 0; sel < 2; sel++) {
        const __nv_bfloat16* src = sel ? Bl : Bh;
        uint32_t (*dst)[18] = sel ? Bs1 : Bs0;
        const uint4* gp = (const uint4*)&src[(size_t)(n0 + lrow) * KTOT + k0 + lhalf * 16];
        uint4 v0 = gp[0], v1 = gp[1];
        uint32_t* d = &dst[lrow][lhalf * 8];
        d[0] = v0.x; d[1] = v0.y; d[2] = v0.z; d[3] = v0.w;
        d[4] = v1.x; d[5] = v1.y; d[6] = v1.z; d[7] = v1.w;
    }
}

template<int KTOT, int BN, int AMODE>
__global__ __launch_bounds__(256) void gemm_mma(
        const void* __restrict__ A1, const void* __restrict__ A2,
        const __nv_bfloat16* __restrict__ Bh, const __nv_bfloat16* __restrict__ Bl,
        float* __restrict__ C, int Nn) {
    __shared__ uint32_t As[2][128][18];
    __shared__ uint32_t Bs[2][BN][18];
    const int tid = threadIdx.x;
    const int m0 = blockIdx.x * 128, n0 = blockIdx.y * BN;
    const int wid = tid >> 5, lane = tid & 31;
    constexpr int NI = (BN == 128) ? 4 : 2;
    const int wm0 = (BN == 128) ? (wid & 1) * 64 : (wid & 3) * 32;
    const int wn0 = (BN == 128) ? (wid >> 1) * 32 : (wid >> 2) * 32;
    const int gr = lane >> 2, cp = lane & 3;
    float acc[NI][4][4] = {};

    const int lrow = tid >> 1, lhalf = tid & 1;
    for (int k0 = 0; k0 < KTOT; k0 += 32) {
        if (AMODE == 0) {
#pragma unroll
            for (int sel = 0; sel < 2; sel++) {
                const __nv_bfloat16* src = sel ? (const __nv_bfloat16*)A2
                                               : (const __nv_bfloat16*)A1;
                const uint4* gp = (const uint4*)&src[(size_t)(m0 + lrow) * KTOT + k0 + lhalf * 16];
                uint4 v0 = gp[0], v1 = gp[1];
                uint32_t* d = &As[sel][lrow][lhalf * 8];
                d[0] = v0.x; d[1] = v0.y; d[2] = v0.z; d[3] = v0.w;
                d[4] = v1.x; d[5] = v1.y; d[6] = v1.z; d[7] = v1.w;
            }
        } else {
            const uint32_t* src = (const uint32_t*)A1;
            const uint4* gp = (const uint4*)&src[(size_t)(m0 + lrow) * KTOT + k0 + lhalf * 16];
            uint4 p0 = gp[0], p1 = gp[1], p2 = gp[2], p3 = gp[3];
            uint32_t pw[16] = {p0.x,p0.y,p0.z,p0.w, p1.x,p1.y,p1.z,p1.w,
                               p2.x,p2.y,p2.z,p2.w, p3.x,p3.y,p3.z,p3.w};
            uint32_t* dh = &As[0][lrow][lhalf * 8];
            uint32_t* dl = &As[1][lrow][lhalf * 8];
#pragma unroll
            for (int q = 0; q < 8; q++) {
                dh[q] = __byte_perm(pw[2*q], pw[2*q+1], 0x5410);
                dl[q] = __byte_perm(pw[2*q], pw[2*q+1], 0x7632);
            }
        }
        if (BN == 128 || tid < 2 * BN)
            stage_b_tile(Bh, Bl, Bs[0], Bs[1], n0, KTOT, k0, lrow, lhalf);
        __syncthreads();
#pragma unroll
        for (int pass = 0; pass < 3; pass++) {
            uint32_t (*pA)[18] = As[pass == 2 ? 1 : 0];
            uint32_t (*pB)[18] = Bs[pass == 1 ? 1 : 0];
#pragma unroll
            for (int k16 = 0; k16 < 2; k16++) {
                const int kp = k16 * 8;
                uint32_t a[NI][4], bf[4][2];
#pragma unroll
                for (int i = 0; i < NI; i++) {
                    int rbase = wm0 + 16 * i;
                    a[i][0] = pA[rbase + gr][kp + cp];
                    a[i][1] = pA[rbase + gr + 8][kp + cp];
                    a[i][2] = pA[rbase + gr][kp + cp + 4];
                    a[i][3] = pA[rbase + gr + 8][kp + cp + 4];
                }
#pragma unroll
                for (int j = 0; j < 4; j++) {
                    int brow = wn0 + 8 * j + gr;
                    bf[j][0] = pB[brow][kp + cp];
                    bf[j][1] = pB[brow][kp + cp + 4];
                }
#pragma unroll
                for (int i = 0; i < NI; i++)
#pragma unroll
                    for (int j = 0; j < 4; j++)
                        mma16816(acc[i][j], a[i], bf[j]);
            }
        }
        __syncthreads();
    }
#pragma unroll
    for (int i = 0; i < NI; i++) {
#pragma unroll
        for (int j = 0; j < 4; j++) {
            int row = m0 + wm0 + 16 * i + gr;
            int col = n0 + wn0 + 8 * j + cp * 2;
            if (col < Nn) {
                *(float2*)&C[(size_t)row * Nn + col] = make_float2(acc[i][j][0], acc[i][j][1]);
                *(float2*)&C[(size_t)(row + 8) * Nn + col] = make_float2(acc[i][j][2], acc[i][j][3]);
            }
        }
    }
}

// ------------------------- conv + silu + packed split, BOTH dirs ------------
__global__ void k_conv2(const float* __restrict__ cwf, const float* __restrict__ cbf,
                        const float* __restrict__ cwb, const float* __restrict__ cbb) {
    int d = threadIdx.x;
    int t0 = blockIdx.x * 16;
    int b = blockIdx.y;
    float wf0 = cwf[d*4], wf1 = cwf[d*4+1], wf2 = cwf[d*4+2], wf3 = cwf[d*4+3];
    float bf = cbf[d];
    float wb0 = cwb[d*4], wb1 = cwb[d*4+1], wb2 = cwb[d*4+2], wb3 = cwb[d*4+3];
    float bb = cbb[d];
    const float* xp = g_xz + (size_t)(b * LL) * 512 + d;
    float v[7];
#pragma unroll
    for (int j = 0; j < 7; j++) {
        int tt = t0 - 3 + j;
        v[j] = (tt >= 0 && tt < LL) ? xp[(size_t)tt * 512] : 0.f;
    }
#pragma unroll
    for (int i = 0; i < 16; i++) {
        int t = t0 + i;
        float f  = bf + wf0*v[0] + wf1*v[1] + wf2*v[2] + wf3*v[3];
        float bw = bb + wb0*v[6] + wb1*v[5] + wb2*v[4] + wb3*v[3];
        float xf = siluf(f), xb = siluf(bw);
        __nv_bfloat16 h, l;
        bsplit(xf, h, l);
        g_xc32[0][(size_t)(b * LL + t) * DI + d] = pack2(h, l);
        bsplit(xb, h, l);
        g_xc32[1][(size_t)(b * LL + (LL - 1 - t)) * DI + d] = pack2(h, l);
        v[0]=v[1]; v[1]=v[2]; v[2]=v[3]; v[3]=v[4]; v[4]=v[5]; v[5]=v[6];
        int tn = t + 4;
        v[6] = (tn < LL) ? xp[(size_t)tn * 512] : 0.f;
    }
}

// ------------------------- out_proj GEMM + residual + LN2 -------------------
__global__ __launch_bounds__(256) void gemm_out(
        const float* __restrict__ x,
        const float* __restrict__ lw, const float* __restrict__ lb,
        float* __restrict__ out) {
    extern __shared__ __align__(16) char smraw[];
    uint32_t (*As)[128][18] = (uint32_t (*)[128][18])smraw;
    uint32_t (*Bs)[128][18] = (uint32_t (*)[128][18])(smraw + 36864);
    const int tid = threadIdx.x;
    const int m0 = blockIdx.x * 128;
    const int wid = tid >> 5, lane = tid & 31;
    const int wm0 = (wid & 1) * 64, wn0 = (wid >> 1) * 32;
    const int gr = lane >> 2, cp = lane & 3;
    float acc[4][4][4] = {};
    const int lrow = tid >> 1, lhalf = tid & 1;
    const float* Yf = g_ydir[0];
    const float* Yb = g_ydir[1];
    for (int k0 = 0; k0 < DI; k0 += 32) {
        {
            const float4* pf = (const float4*)&Yf[(size_t)(m0 + lrow) * DI + k0 + lhalf * 16];
            const float4* pb = (const float4*)&Yb[(size_t)(m0 + lrow) * DI + k0 + lhalf * 16];
            float v[16];
#pragma unroll
            for (int q = 0; q < 4; q++) {
                float4 a = pf[q], bq = pb[q];
                v[q*4+0] = a.x + bq.x; v[q*4+1] = a.y + bq.y;
                v[q*4+2] = a.z + bq.z; v[q*4+3] = a.w + bq.w;
            }
            uint32_t* dh = &As[0][lrow][lhalf * 8];
            uint32_t* dl = &As[1][lrow][lhalf * 8];
#pragma unroll
            for (int q = 0; q < 8; q++) {
                __nv_bfloat16 h0, l0, h1, l1;
                bsplit(v[2*q], h0, l0);
                bsplit(v[2*q+1], h1, l1);
                dh[q] = pack2(h0, h1);
                dl[q] = pack2(l0, l1);
            }
        }
#pragma unroll
        for (int sel = 0; sel < 2; sel++) {
            const __nv_bfloat16* src = sel ? g_wol : g_woh;
            const uint4* gp = (const uint4*)&src[(size_t)lrow * DI + k0 + lhalf * 16];
            uint4 v0 = gp[0], v1 = gp[1];
            uint32_t* d = &Bs[sel][lrow][lhalf * 8];
            d[0] = v0.x; d[1] = v0.y; d[2] = v0.z; d[3] = v0.w;
            d[4] = v1.x; d[5] = v1.y; d[6] = v1.z; d[7] = v1.w;
        }
        __syncthreads();
#pragma unroll
        for (int pass = 0; pass < 3; pass++) {
            uint32_t (*pA)[18] = As[pass == 2 ? 1 : 0];
            uint32_t (*pB)[18] = Bs[pass == 1 ? 1 : 0];
#pragma unroll
            for (int k16 = 0; k16 < 2; k16++) {
                const int kp = k16 * 8;
                uint32_t a[4][4], bf[4][2];
#pragma unroll
                for (int i = 0; i < 4; i++) {
                    int rbase = wm0 + 16 * i;
                    a[i][0] = pA[rbase + gr][kp + cp];
                    a[i][1] = pA[rbase + gr + 8][kp + cp];
                    a[i][2] = pA[rbase + gr][kp + cp + 4];
                    a[i][3] = pA[rbase + gr + 8][kp + cp + 4];
                }
#pragma unroll
                for (int j = 0; j < 4; j++) {
                    int brow = wn0 + 8 * j + gr;
                    bf[j][0] = pB[brow][kp + cp];
                    bf[j][1] = pB[brow][kp + cp + 4];
                }
#pragma unroll
                for (int i = 0; i < 4; i++)
#pragma unroll
                    for (int j = 0; j < 4; j++)
                        mma16816(acc[i][j], a[i], bf[j]);
            }
        }
        __syncthreads();
    }
    // ---- epilogue: acc -> smem, + residual, LN over channels, write out ----
    float (*sD)[129] = (float (*)[129])smraw;
    float (*prs)[2] = (float (*)[2])(smraw + 66048);
    float (*prq)[2] = (float (*)[2])(smraw + 67072);
    float* mu   = (float*)(smraw + 68096);
    float* rstd = (float*)(smraw + 68608);
#pragma unroll
    for (int i = 0; i < 4; i++) {
#pragma unroll
        for (int j = 0; j < 4; j++) {
            int row = wm0 + 16 * i + gr;
            int col = wn0 + 8 * j + cp * 2;
            sD[row][col]     = acc[i][j][0];
            sD[row][col + 1] = acc[i][j][1];
            sD[row + 8][col]     = acc[i][j][2];
            sD[row + 8][col + 1] = acc[i][j][3];
        }
    }
    __syncthreads();
    const int b  = m0 / LL;
    const int l0 = m0 % LL;
#pragma unroll
    for (int i = 0; i < 64; i++) {
        int e = tid + i * 256;
        int l = e & 127, c = e >> 7;
        sD[l][c] += x[(size_t)(b * DM + c) * LL + l0 + l];
    }
    __syncthreads();
    {
        int r = tid >> 1, half = tid & 1;
        float su = 0.f, sq = 0.f;
#pragma unroll
        for (int cc = 0; cc < 64; cc++) {
            float v = sD[r][half * 64 + cc];
            su += v; sq = fmaf(v, v, sq);
        }
        prs[r][half] = su; prq[r][half] = sq;
    }
    __syncthreads();
    if (tid < 128) {
        float su = prs[tid][0] + prs[tid][1];
        float sq = prq[tid][0] + prq[tid][1];
        float m = su * (1.f / DM);
        float var = sq * (1.f / DM) - m * m;
        mu[tid] = m; rstd[tid] = rsqrtf(var + 1e-5f);
    }
    __syncthreads();
#pragma unroll
    for (int i = 0; i < 64; i++) {
        int e = tid + i * 256;
        int l = e & 127, c = e >> 7;
        out[(size_t)(b * DM + c) * LL + l0 + l] =
            (sD[l][c] - mu[l]) * rstd[l] * lw[c] + lb[c];
    }
}

// ------------------------- scan pass 1 (inline dt) --------------------------
__global__ void k_scan1(const float* __restrict__ Alog_f, const float* __restrict__ Alog_b,
                        const float* __restrict__ dtw_f, const float* __restrict__ dtb_f,
                        const float* __restrict__ dtw_b, const float* __restrict__ dtb_b) {
    int ch = blockIdx.x, b = blockIdx.y, dir = blockIdx.z, d = threadIdx.x;
    const float* Alog = dir ? Alog_b : Alog_f;
    const float* dtw  = dir ? dtw_b : dtw_f;
    float dtb = (dir ? dtb_b : dtb_f)[d];
    __shared__ __align__(16) float sd[CHUNK][24];
    int t0 = ch * CHUNK;
    const float* gsrc = g_dbl[dir] + (size_t)(b * LL + t0) * NDBL;
    for (int i = threadIdx.x; i < CHUNK * 6; i += 256) {
        int t = i / 6, q = i - t * 6;
        *((float4*)&sd[t][q * 4]) = *((const float4*)&gsrc[t * NDBL + q * 4]);
    }
    float Ad[NS], h[NS], wdt[DTR];
    bool fast = true;
#pragma unroll
    for (int n = 0; n < NS; n++) {
        Ad[n] = -__expf(Alog[d * NS + n]);
        fast = fast && (fabsf(Ad[n] + (float)(n + 1)) <= 1e-5f * (n + 1));
    }
#pragma unroll
    for (int i = 0; i < DTR; i++) wdt[i] = dtw[d * DTR + i];
#pragma unroll
    for (int n = 0; n < NS; n++) h[n] = 0.f;
    const uint32_t* xc = g_xc32[dir] + (size_t)(b * LL + t0) * DI + d;
    float rP = 1.f, S = 0.f;
    __syncthreads();
    if (fast) {
#pragma unroll 2
        for (int t = 0; t < CHUNK; t++) {
            const float* row = sd[t];
            float4 d0 = *(const float4*)&row[0];
            float4 d1 = *(const float4*)&row[4];
            float a = dtb;
            a = fmaf(wdt[0], d0.x, a); a = fmaf(wdt[1], d0.y, a);
            a = fmaf(wdt[2], d0.z, a); a = fmaf(wdt[3], d0.w, a);
            a = fmaf(wdt[4], d1.x, a); a = fmaf(wdt[5], d1.y, a);
            a = fmaf(wdt[6], d1.z, a); a = fmaf(wdt[7], d1.w, a);
            float r, dt; dt_math(a, r, dt);
            float cB = dt * unpack_sum(xc[(size_t)t * DI]);
            float4 B0 = *(const float4*)&row[8],  B1 = *(const float4*)&row[12];
            float4 B2 = *(const float4*)&row[16], B3 = *(const float4*)&row[20];
            float Bv[16] = {B0.x,B0.y,B0.z,B0.w, B1.x,B1.y,B1.z,B1.w,
                            B2.x,B2.y,B2.z,B2.w, B3.x,B3.y,B3.z,B3.w};
            float wv[NS];
            mkpow(r, wv);
            rP *= r;
#pragma unroll
            for (int n = 0; n < NS; n++)
                h[n] = fmaf(wv[n], h[n], cB * Bv[n]);
        }
    } else {
        for (int t = 0; t < CHUNK; t++) {
            const float* row = sd[t];
            float a = dtb;
#pragma unroll
            for (int i = 0; i < DTR; i++) a = fmaf(wdt[i], row[i], a);
            float r, dt; dt_math(a, r, dt);
            float cB = dt * unpack_sum(xc[(size_t)t * DI]);
            S += dt;
#pragma unroll
            for (int n = 0; n < NS; n++)
                h[n] = fmaf(__expf(dt * Ad[n]), h[n], cB * row[8 + n]);
        }
    }
    int base = ((dir * NCH + ch) * BB + b) * NS;
    if (fast) {
        float pw[NS];
        mkpow(rP, pw);
#pragma unroll
        for (int n = 0; n < NS; n++) {
            g_hend[(base + n) * DI + d] = h[n];
            g_P[(base + n) * DI + d]    = pw[n];
        }
    } else {
#pragma unroll
        for (int n = 0; n < NS; n++) {
            g_hend[(base + n) * DI + d] = h[n];
            g_P[(base + n) * DI + d]    = __expf(Ad[n] * S);
        }
    }
}

// ------------------------- scan pass 2 --------------------------------------
__global__ void k_scan2() {
    int d = threadIdx.x;
    int n   = blockIdx.x & 15;
    int b   = (blockIdx.x >> 4) & 3;
    int dir = blockIdx.x >> 6;
    float hs = 0.f;
    for (int ch = 0; ch < NCH; ch++) {
        int idx = (((dir * NCH + ch) * BB + b) * NS + n) * DI + d;
        g_hinit[idx] = hs;
        hs = fmaf(g_P[idx], hs, g_hend[idx]);
    }
}

// ------------------------- scan pass 3 (inline dt, emit y) ------------------
__global__ void k_scan3(const float* __restrict__ Alog_f, const float* __restrict__ Dsk_f,
                        const float* __restrict__ Alog_b, const float* __restrict__ Dsk_b,
                        const float* __restrict__ dtw_f, const float* __restrict__ dtb_f,
                        const float* __restrict__ dtw_b, const float* __restrict__ dtb_b) {
    int ch = blockIdx.x, b = blockIdx.y, dir = blockIdx.z, d = threadIdx.x;
    const float* Alog = dir ? Alog_b : Alog_f;
    const float* dtw  = dir ? dtw_b : dtw_f;
    float dtb = (dir ? dtb_b : dtb_f)[d];
    float Dd  = (dir ? Dsk_b : Dsk_f)[d];
    __shared__ __align__(16) float sd[CHUNK][40];
    int t0 = ch * CHUNK;
    const float* gsrc = g_dbl[dir] + (size_t)(b * LL + t0) * NDBL;
    for (int i = threadIdx.x; i < CHUNK * 10; i += 256) {
        int t = i / 10, q = i - t * 10;
        *((float4*)&sd[t][q * 4]) = *((const float4*)&gsrc[t * NDBL + q * 4]);
    }
    float Ad[NS], h[NS], wdt[DTR];
    bool fast = true;
#pragma unroll
    for (int n = 0; n < NS; n++) {
        Ad[n] = -__expf(Alog[d * NS + n]);
        fast = fast && (fabsf(Ad[n] + (float)(n + 1)) <= 1e-5f * (n + 1));
    }
#pragma unroll
    for (int i = 0; i < DTR; i++) wdt[i] = dtw[d * DTR + i];
    int base = ((dir * NCH + ch) * BB + b) * NS;
#pragma unroll
    for (int n = 0; n < NS; n++) h[n] = g_hinit[(base + n) * DI + d];
    const uint32_t* xc = g_xc32[dir] + (size_t)(b * LL + t0) * DI + d;
    const float* xzz = g_xz + (size_t)b * LL * 512 + DI + d;
    float* yout = g_ydir[dir] + (size_t)b * LL * DI + d;
    __syncthreads();
    if (fast) {
#pragma unroll 2
        for (int t = 0; t < CHUNK; t++) {
            const float* row = sd[t];
            float4 d0 = *(const float4*)&row[0];
            float4 d1 = *(const float4*)&row[4];
            float a = dtb;
            a = fmaf(wdt[0], d0.x, a); a = fmaf(wdt[1], d0.y, a);
            a = fmaf(wdt[2], d0.z, a); a = fmaf(wdt[3], d0.w, a);
            a = fmaf(wdt[4], d1.x, a); a = fmaf(wdt[5], d1.y, a);
            a = fmaf(wdt[6], d1.z, a); a = fmaf(wdt[7], d1.w, a);
            float r, dt; dt_math(a, r, dt);
            float xv = unpack_sum(xc[(size_t)t * DI]);
            float cB = dt * xv;
            float4 B0 = *(const float4*)&row[8],  B1 = *(const float4*)&row[12];
            float4 B2 = *(const float4*)&row[16], B3 = *(const float4*)&row[20];
            float4 C0 = *(const float4*)&row[24], C1 = *(const float4*)&row[28];
            float4 C2 = *(const float4*)&row[32], C3 = *(const float4*)&row[36];
            float Bv[16] = {B0.x,B0.y,B0.z,B0.w, B1.x,B1.y,B1.z,B1.w,
                            B2.x,B2.y,B2.z,B2.w, B3.x,B3.y,B3.z,B3.w};
            float Cv[16] = {C0.x,C0.y,C0.z,C0.w, C1.x,C1.y,C1.z,C1.w,
                            C2.x,C2.y,C2.z,C2.w, C3.x,C3.y,C3.z,C3.w};
            float wv[NS];
            mkpow(r, wv);
            float y = 0.f;
#pragma unroll
            for (int n = 0; n < NS; n++) {
                h[n] = fmaf(wv[n], h[n], cB * Bv[n]);
                y = fmaf(h[n], Cv[n], y);
            }
            int torig = dir ? (LL - 1 - (t0 + t)) : (t0 + t);
            float zv = xzz[(size_t)torig * 512];
            yout[(size_t)torig * DI] = (y + xv * Dd) * siluf(zv);
        }
    } else {
        for (int t = 0; t < CHUNK; t++) {
            const float* row = sd[t];
            float a = dtb;
#pragma unroll
            for (int i = 0; i < DTR; i++) a = fmaf(wdt[i], row[i], a);
            float r, dt; dt_math(a, r, dt);
            float xv = unpack_sum(xc[(size_t)t * DI]);
            float cB = dt * xv;
            float y = 0.f;
#pragma unroll
            for (int n = 0; n < NS; n++) {
                h[n] = fmaf(__expf(dt * Ad[n]), h[n], cB * row[8 + n]);
                y = fmaf(h[n], row[24 + n], y);
            }
            int torig = dir ? (LL - 1 - (t0 + t)) : (t0 + t);
            float zv = xzz[(size_t)torig * 512];
            yout[(size_t)torig * DI] = (y + xv * Dd) * siluf(zv);
        }
    }
}

// ------------------------- launch ------------------------------------------
extern "C" void kernel_launch(void* const* d_in, const int* in_sizes, int n_in,
                              void* d_out, int out_size) {
    const float* x        = (const float*)d_in[0];
    const float* ln1_w    = (const float*)d_in[1];
    const float* ln1_b    = (const float*)d_in[2];
    const float* ln2_w    = (const float*)d_in[3];
    const float* ln2_b    = (const float*)d_in[4];
    const float* in_proj  = (const float*)d_in[5];
    const float* out_proj = (const float*)d_in[6];
    const float* conv_w_f = (const float*)d_in[7];
    const float* conv_b_f = (const float*)d_in[8];
    const float* xproj_f  = (const float*)d_in[9];
    const float* dtw_f    = (const float*)d_in[10];
    const float* dtb_f    = (const float*)d_in[11];
    const float* Alog_f   = (const float*)d_in[12];
    const float* D_f      = (const float*)d_in[13];
    const float* conv_w_b = (const float*)d_in[14];
    const float* conv_b_b = (const float*)d_in[15];
    const float* xproj_b  = (const float*)d_in[16];
    const float* dtw_b    = (const float*)d_in[17];
    const float* dtb_b    = (const float*)d_in[18];
    const float* Alog_b   = (const float*)d_in[19];
    const float* D_b      = (const float*)d_in[20];
    float* out = (float*)d_out;

    static bool attr_done = false;
    if (!attr_done) {
        cudaFuncSetAttribute(gemm_out, cudaFuncAttributeMaxDynamicSharedMemorySize, OUT_SMEM);
        attr_done = true;
    }

    float *p_xz, *p_dbl;
    __nv_bfloat16 *p_xnh, *p_xnl, *p_wih, *p_wil, *p_xpwh, *p_xpwl;
    uint32_t *p_xc32;
    cudaGetSymbolAddress((void**)&p_xz,   g_xz);
    cudaGetSymbolAddress((void**)&p_dbl,  g_dbl);
    cudaGetSymbolAddress((void**)&p_xnh,  g_xnh);
    cudaGetSymbolAddress((void**)&p_xnl,  g_xnl);
    cudaGetSymbolAddress((void**)&p_wih,  g_wih);
    cudaGetSymbolAddress((void**)&p_wil,  g_wil);
    cudaGetSymbolAddress((void**)&p_xpwh, g_xpwh);
    cudaGetSymbolAddress((void**)&p_xpwl, g_xpwl);
    cudaGetSymbolAddress((void**)&p_xc32, g_xc32);

    // 0. weight bf16 splits
    int wtot = 512 * 128 + 128 * 256 + 2 * 64 * 256;
    k_wconv<<<(wtot + 255) / 256, 256>>>(in_proj, out_proj, xproj_f, xproj_b);

    // 1. LN1 + transpose + split
    k_ln1<<<MTOK / 64, 256>>>(x, ln1_w, ln1_b);

    // 2. in_proj: [32768,128] x [512,128]^T -> g_xz
    gemm_mma<DM, 128, 0><<<dim3(MTOK / 128, 4), 256>>>(p_xnh, p_xnl, p_wih, p_wil,
                                                       p_xz, 2 * DI);

    // 3. conv + silu + packed split, both dirs
    k_conv2<<<dim3(LL / 16, BB), 256>>>(conv_w_f, conv_b_f, conv_w_b, conv_b_b);

    // 4. x_proj per dir (BN=64, packed A): -> g_dbl
    gemm_mma<DI, 64, 1><<<dim3(MTOK / 128, 1), 256>>>(
        p_xc32, nullptr, p_xpwh, p_xpwl, p_dbl, NDBL);
    gemm_mma<DI, 64, 1><<<dim3(MTOK / 128, 1), 256>>>(
        p_xc32 + (size_t)MTOK * DI, nullptr,
        p_xpwh + (size_t)64 * 256, p_xpwl + (size_t)64 * 256,
        p_dbl + (size_t)MTOK * NDBL, NDBL);

    // 5-7. chunked selective scan (dt inline)
    k_scan1<<<dim3(NCH, BB, 2), 256>>>(Alog_f, Alog_b, dtw_f, dtb_f, dtw_b, dtb_b);
    k_scan2<<<2 * BB * NS, 256>>>();
    k_scan3<<<dim3(NCH, BB, 2), 256>>>(Alog_f, D_f, Alog_b, D_b,
                                       dtw_f, dtb_f, dtw_b, dtb_b);

    // 8. out_proj + residual + LN2 -> final output
    gemm_out<<<dim3(MTOK / 128, 1), 256, OUT_SMEM>>>(x, ln2_w, ln2_b, out);
}

// round 14
// speedup vs baseline: 1.0968x; 1.0037x over previous
#include <cuda_runtime.h>
#include <cuda_bf16.h>
#include <cstdint>

// ---------------------------------------------------------------------------
// MambaLayer (bidirectional VideoMamba), B200 sm_100 — round 14
// (round-13 source resubmitted after broker infra failure)
// LN1 fused into in_proj GEMM; z pre-gated; conv interior fast path
// ---------------------------------------------------------------------------

#define BB   4
#define DM   128
#define LL   8192
#define DI   256
#define NS   16
#define DTR  8
#define NDBL 40
#define MTOK (BB*LL)
#define CHUNK 64
#define NCH  (LL/CHUNK)
#define OUT_SMEM 73728
#define IN_SMEM  104960   // xn 128x133 f32 (68096) + As 18432 + Bs 18432

// ------------------------- scratch (static device mem) ---------------------
__device__ float          g_xz    [MTOK*2*DI];      // z half pre-gated by silu
__device__ float          g_dbl   [2][MTOK*NDBL];
__device__ uint32_t       g_xc32  [2][MTOK*DI];     // packed bf16 (hi | lo<<16)
__device__ float          g_ydir  [2][MTOK*DI];
__device__ float          g_hend  [2*NCH*BB*NS*DI];
__device__ float          g_P     [2*NCH*BB*NS*DI];
__device__ float          g_hinit [2*NCH*BB*NS*DI];
__device__ __nv_bfloat16  g_wih[512*128],  g_wil[512*128];
__device__ __nv_bfloat16  g_woh[128*256],  g_wol[128*256];
__device__ __nv_bfloat16  g_xpwh[2][64*256], g_xpwl[2][64*256]; // rows>=40 zero

// ------------------------- math helpers -------------------------------------
__device__ __forceinline__ float siluf(float x) {
    return __fdividef(x, 1.f + __expf(-x));
}
__device__ __forceinline__ void mkpow(float r, float* w) {
    float r2 = r * r, r3 = r2 * r, r4 = r2 * r2;
    float r5 = r4 * r, r6 = r4 * r2, r7 = r4 * r3, r8 = r4 * r4;
    w[0]=r;  w[1]=r2; w[2]=r3; w[3]=r4; w[4]=r5; w[5]=r6; w[6]=r7; w[7]=r8;
    w[8]=r8*r; w[9]=r8*r2; w[10]=r8*r3; w[11]=r8*r4;
    w[12]=r8*r5; w[13]=r8*r6; w[14]=r8*r7; w[15]=r8*r8;
}
__device__ __forceinline__ void bsplit(float v, __nv_bfloat16& hi, __nv_bfloat16& lo) {
    hi = __float2bfloat16(v);
    lo = __float2bfloat16(v - __bfloat162float(hi));
}
__device__ __forceinline__ uint32_t pack2(__nv_bfloat16 a, __nv_bfloat16 b) {
    return (uint32_t)__bfloat16_as_ushort(a) | ((uint32_t)__bfloat16_as_ushort(b) << 16);
}
__device__ __forceinline__ float unpack_sum(uint32_t p) {
    __nv_bfloat16 h = __ushort_as_bfloat16((unsigned short)(p & 0xffffu));
    __nv_bfloat16 l = __ushort_as_bfloat16((unsigned short)(p >> 16));
    return __bfloat162float(h) + __bfloat162float(l);
}
__device__ __forceinline__ void dt_math(float a, float& r, float& dt) {
    float e = __expf(a);
    r = __fdividef(1.f, 1.f + e);
    if (a > 15.f)      dt = a;
    else if (a > -3.f) dt = __logf(1.f + e);
    else               dt = e * fmaf(e, fmaf(e, 0.33333334f, -0.5f), 1.f);
}
__device__ __forceinline__ void mma16816(float* c, const uint32_t* a, const uint32_t* b) {
    asm volatile(
        "mma.sync.aligned.m16n8k16.row.col.f32.bf16.bf16.f32 "
        "{%0,%1,%2,%3}, {%4,%5,%6,%7}, {%8,%9}, {%0,%1,%2,%3};"
        : "+f"(c[0]), "+f"(c[1]), "+f"(c[2]), "+f"(c[3])
        : "r"(a[0]), "r"(a[1]), "r"(a[2]), "r"(a[3]), "r"(b[0]), "r"(b[1]));
}

// ------------------------- weight convert -----------------------------------
__global__ void k_wconv(const float* __restrict__ wi, const float* __restrict__ wo,
                        const float* __restrict__ xpf, const float* __restrict__ xpb) {
    int i = blockIdx.x * 256 + threadIdx.x;
    if (i < 512 * 128) { bsplit(wi[i], g_wih[i], g_wil[i]); return; }
    int j = i - 512 * 128;
    if (j < 128 * 256) { bsplit(wo[j], g_woh[j], g_wol[j]); return; }
    int k = j - 128 * 256;
    if (k < 2 * 64 * 256) {
        int dir = k / (64 * 256);
        int idx = k - dir * 64 * 256;
        int n = idx >> 8;
        const float* src = dir ? xpb : xpf;
        float v = (n < NDBL) ? src[idx] : 0.f;
        bsplit(v, g_xpwh[dir][idx], g_xpwl[dir][idx]);
    }
}

// ------------------------- in_proj GEMM with fused LN1 ----------------------
// Stages x transposed tile, LN per token in-block, normalize+split in staging.
// Epilogue applies silu to the z half (n0 >= 256).
__global__ __launch_bounds__(256) void gemm_in_ln(
        const float* __restrict__ x,
        const float* __restrict__ lw, const float* __restrict__ lb,
        float* __restrict__ C) {
    extern __shared__ __align__(16) char smraw[];
    float (*xn)[133] = (float (*)[133])smraw;
    uint32_t (*As)[128][18] = (uint32_t (*)[128][18])(smraw + 68096);
    uint32_t (*Bs)[128][18] = (uint32_t (*)[128][18])(smraw + 68096 + 18432);
    __shared__ float prs[128][2], prq[128][2], mu[128], rstd[128];
    const int tid = threadIdx.x;
    const int m0 = blockIdx.x * 128, n0 = blockIdx.y * 128;
    const int b = m0 / LL, l0 = m0 % LL;
    // 1. load x tile transposed (coalesced over l)
#pragma unroll
    for (int i = 0; i < 64; i++) {
        int e = tid + i * 256;
        int l = e & 127, c = e >> 7;
        xn[l][c] = x[(size_t)(b * DM + c) * LL + l0 + l];
    }
    __syncthreads();
    // 2. LN stats per token
    {
        int r = tid >> 1, half = tid & 1;
        float su = 0.f, sq = 0.f;
#pragma unroll
        for (int cc = 0; cc < 64; cc++) {
            float v = xn[r][half * 64 + cc];
            su += v; sq = fmaf(v, v, sq);
        }
        prs[r][half] = su; prq[r][half] = sq;
    }
    __syncthreads();
    if (tid < 128) {
        float su = prs[tid][0] + prs[tid][1];
        float sq = prq[tid][0] + prq[tid][1];
        float m = su * (1.f / DM);
        float var = sq * (1.f / DM) - m * m;
        mu[tid] = m; rstd[tid] = rsqrtf(var + 1e-5f);
    }
    __syncthreads();
    // 3. GEMM
    const int wid = tid >> 5, lane = tid & 31;
    const int wm0 = (wid & 1) * 64, wn0 = (wid >> 1) * 32;
    const int gr = lane >> 2, cp = lane & 3;
    float acc[4][4][4] = {};
    const int lrow = tid >> 1, lhalf = tid & 1;
    const float mm = mu[lrow], ms = rstd[lrow];
    for (int k0 = 0; k0 < DM; k0 += 32) {
        {
            const int c0 = k0 + lhalf * 16;
            uint32_t* dh = &As[0][lrow][lhalf * 8];
            uint32_t* dl = &As[1][lrow][lhalf * 8];
#pragma unroll
            for (int q = 0; q < 8; q++) {
                int c = c0 + q * 2;
                float v0 = (xn[lrow][c]     - mm) * ms * lw[c]     + lb[c];
                float v1 = (xn[lrow][c + 1] - mm) * ms * lw[c + 1] + lb[c + 1];
                __nv_bfloat16 h0, lo0, h1, lo1;
                bsplit(v0, h0, lo0);
                bsplit(v1, h1, lo1);
                dh[q] = pack2(h0, h1);
                dl[q] = pack2(lo0, lo1);
            }
        }
#pragma unroll
        for (int sel = 0; sel < 2; sel++) {
            const __nv_bfloat16* src = sel ? g_wil : g_wih;
            const uint4* gp = (const uint4*)&src[(size_t)(n0 + lrow) * DM + k0 + lhalf * 16];
            uint4 v0 = gp[0], v1 = gp[1];
            uint32_t* d = &Bs[sel][lrow][lhalf * 8];
            d[0] = v0.x; d[1] = v0.y; d[2] = v0.z; d[3] = v0.w;
            d[4] = v1.x; d[5] = v1.y; d[6] = v1.z; d[7] = v1.w;
        }
        __syncthreads();
#pragma unroll
        for (int pass = 0; pass < 3; pass++) {
            uint32_t (*pA)[18] = As[pass == 2 ? 1 : 0];
            uint32_t (*pB)[18] = Bs[pass == 1 ? 1 : 0];
#pragma unroll
            for (int k16 = 0; k16 < 2; k16++) {
                const int kp = k16 * 8;
                uint32_t a[4][4], bf[4][2];
#pragma unroll
                for (int i = 0; i < 4; i++) {
                    int rbase = wm0 + 16 * i;
                    a[i][0] = pA[rbase + gr][kp + cp];
                    a[i][1] = pA[rbase + gr + 8][kp + cp];
                    a[i][2] = pA[rbase + gr][kp + cp + 4];
                    a[i][3] = pA[rbase + gr + 8][kp + cp + 4];
                }
#pragma unroll
                for (int j = 0; j < 4; j++) {
                    int brow = wn0 + 8 * j + gr;
                    bf[j][0] = pB[brow][kp + cp];
                    bf[j][1] = pB[brow][kp + cp + 4];
                }
#pragma unroll
                for (int i = 0; i < 4; i++)
#pragma unroll
                    for (int j = 0; j < 4; j++)
                        mma16816(acc[i][j], a[i], bf[j]);
            }
        }
        __syncthreads();
    }
    // 4. epilogue: silu-gate the z half (n0 >= 256)
    const bool zh = (n0 >= 256);
#pragma unroll
    for (int i = 0; i < 4; i++) {
#pragma unroll
        for (int j = 0; j < 4; j++) {
            int row = m0 + wm0 + 16 * i + gr;
            int col = n0 + wn0 + 8 * j + cp * 2;
            float2 c0 = make_float2(acc[i][j][0], acc[i][j][1]);
            float2 c1 = make_float2(acc[i][j][2], acc[i][j][3]);
            if (zh) {
                c0.x = siluf(c0.x); c0.y = siluf(c0.y);
                c1.x = siluf(c1.x); c1.y = siluf(c1.y);
            }
            *(float2*)&C[(size_t)row * 512 + col] = c0;
            *(float2*)&C[(size_t)(row + 8) * 512 + col] = c1;
        }
    }
}

// ------------------------- x_proj GEMM (packed A, BN=64) --------------------
template<int KTOT, int BN>
__global__ __launch_bounds__(256) void gemm_xp(
        const uint32_t* __restrict__ A1,
        const __nv_bfloat16* __restrict__ Bh, const __nv_bfloat16* __restrict__ Bl,
        float* __restrict__ C, int Nn) {
    __shared__ uint32_t As[2][128][18];
    __shared__ uint32_t Bs[2][BN][18];
    const int tid = threadIdx.x;
    const int m0 = blockIdx.x * 128, n0 = 0;
    const int wid = tid >> 5, lane = tid & 31;
    const int wm0 = (wid & 3) * 32, wn0 = (wid >> 2) * 32;
    const int gr = lane >> 2, cp = lane & 3;
    float acc[2][4][4] = {};
    const int lrow = tid >> 1, lhalf = tid & 1;
    for (int k0 = 0; k0 < KTOT; k0 += 32) {
        {
            const uint4* gp = (const uint4*)&A1[(size_t)(m0 + lrow) * KTOT + k0 + lhalf * 16];
            uint4 p0 = gp[0], p1 = gp[1], p2 = gp[2], p3 = gp[3];
            uint32_t pw[16] = {p0.x,p0.y,p0.z,p0.w, p1.x,p1.y,p1.z,p1.w,
                               p2.x,p2.y,p2.z,p2.w, p3.x,p3.y,p3.z,p3.w};
            uint32_t* dh = &As[0][lrow][lhalf * 8];
            uint32_t* dl = &As[1][lrow][lhalf * 8];
#pragma unroll
            for (int q = 0; q < 8; q++) {
                dh[q] = __byte_perm(pw[2*q], pw[2*q+1], 0x5410);
                dl[q] = __byte_perm(pw[2*q], pw[2*q+1], 0x7632);
            }
        }
        if (tid < 2 * BN) {
#pragma unroll
            for (int sel = 0; sel < 2; sel++) {
                const __nv_bfloat16* src = sel ? Bl : Bh;
                const uint4* gp = (const uint4*)&src[(size_t)(n0 + lrow) * KTOT + k0 + lhalf * 16];
                uint4 v0 = gp[0], v1 = gp[1];
                uint32_t* d = &Bs[sel][lrow][lhalf * 8];
                d[0] = v0.x; d[1] = v0.y; d[2] = v0.z; d[3] = v0.w;
                d[4] = v1.x; d[5] = v1.y; d[6] = v1.z; d[7] = v1.w;
            }
        }
        __syncthreads();
#pragma unroll
        for (int pass = 0; pass < 3; pass++) {
            uint32_t (*pA)[18] = As[pass == 2 ? 1 : 0];
            uint32_t (*pB)[18] = Bs[pass == 1 ? 1 : 0];
#pragma unroll
            for (int k16 = 0; k16 < 2; k16++) {
                const int kp = k16 * 8;
                uint32_t a[2][4], bf[4][2];
#pragma unroll
                for (int i = 0; i < 2; i++) {
                    int rbase = wm0 + 16 * i;
                    a[i][0] = pA[rbase + gr][kp + cp];
                    a[i][1] = pA[rbase + gr + 8][kp + cp];
                    a[i][2] = pA[rbase + gr][kp + cp + 4];
                    a[i][3] = pA[rbase + gr + 8][kp + cp + 4];
                }
#pragma unroll
                for (int j = 0; j < 4; j++) {
                    int brow = wn0 + 8 * j + gr;
                    bf[j][0] = pB[brow][kp + cp];
                    bf[j][1] = pB[brow][kp + cp + 4];
                }
#pragma unroll
                for (int i = 0; i < 2; i++)
#pragma unroll
                    for (int j = 0; j < 4; j++)
                        mma16816(acc[i][j], a[i], bf[j]);
            }
        }
        __syncthreads();
    }
#pragma unroll
    for (int i = 0; i < 2; i++) {
#pragma unroll
        for (int j = 0; j < 4; j++) {
            int row = m0 + wm0 + 16 * i + gr;
            int col = wn0 + 8 * j + cp * 2;
            if (col < Nn) {
                *(float2*)&C[(size_t)row * Nn + col] = make_float2(acc[i][j][0], acc[i][j][1]);
                *(float2*)&C[(size_t)(row + 8) * Nn + col] = make_float2(acc[i][j][2], acc[i][j][3]);
            }
        }
    }
}

// ------------------------- conv + silu + packed split, BOTH dirs ------------
__global__ void k_conv2(const float* __restrict__ cwf, const float* __restrict__ cbf,
                        const float* __restrict__ cwb, const float* __restrict__ cbb) {
    int d = threadIdx.x;
    int t0 = blockIdx.x * 16;
    int b = blockIdx.y;
    float wf0 = cwf[d*4], wf1 = cwf[d*4+1], wf2 = cwf[d*4+2], wf3 = cwf[d*4+3];
    float bf = cbf[d];
    float wb0 = cwb[d*4], wb1 = cwb[d*4+1], wb2 = cwb[d*4+2], wb3 = cwb[d*4+3];
    float bb = cbb[d];
    const float* xp = g_xz + (size_t)(b * LL) * 512 + d;
    float v[7];
    const bool edge = (blockIdx.x == 0) || (blockIdx.x == gridDim.x - 1);
    if (edge) {
#pragma unroll
        for (int j = 0; j < 7; j++) {
            int tt = t0 - 3 + j;
            v[j] = (tt >= 0 && tt < LL) ? xp[(size_t)tt * 512] : 0.f;
        }
#pragma unroll
        for (int i = 0; i < 16; i++) {
            int t = t0 + i;
            float f  = bf + wf0*v[0] + wf1*v[1] + wf2*v[2] + wf3*v[3];
            float bw = bb + wb0*v[6] + wb1*v[5] + wb2*v[4] + wb3*v[3];
            __nv_bfloat16 h, l;
            bsplit(siluf(f), h, l);
            g_xc32[0][(size_t)(b * LL + t) * DI + d] = pack2(h, l);
            bsplit(siluf(bw), h, l);
            g_xc32[1][(size_t)(b * LL + (LL - 1 - t)) * DI + d] = pack2(h, l);
            v[0]=v[1]; v[1]=v[2]; v[2]=v[3]; v[3]=v[4]; v[4]=v[5]; v[5]=v[6];
            int tn = t + 4;
            v[6] = (tn < LL) ? xp[(size_t)tn * 512] : 0.f;
        }
    } else {
#pragma unroll
        for (int j = 0; j < 7; j++)
            v[j] = xp[(size_t)(t0 - 3 + j) * 512];
#pragma unroll
        for (int i = 0; i < 16; i++) {
            int t = t0 + i;
            float f  = bf + wf0*v[0] + wf1*v[1] + wf2*v[2] + wf3*v[3];
            float bw = bb + wb0*v[6] + wb1*v[5] + wb2*v[4] + wb3*v[3];
            __nv_bfloat16 h, l;
            bsplit(siluf(f), h, l);
            g_xc32[0][(size_t)(b * LL + t) * DI + d] = pack2(h, l);
            bsplit(siluf(bw), h, l);
            g_xc32[1][(size_t)(b * LL + (LL - 1 - t)) * DI + d] = pack2(h, l);
            v[0]=v[1]; v[1]=v[2]; v[2]=v[3]; v[3]=v[4]; v[4]=v[5]; v[5]=v[6];
            v[6] = xp[(size_t)(t + 4) * 512];
        }
    }
}

// ------------------------- out_proj GEMM + residual + LN2 -------------------
__global__ __launch_bounds__(256) void gemm_out(
        const float* __restrict__ x,
        const float* __restrict__ lw, const float* __restrict__ lb,
        float* __restrict__ out) {
    extern __shared__ __align__(16) char smraw[];
    uint32_t (*As)[128][18] = (uint32_t (*)[128][18])smraw;
    uint32_t (*Bs)[128][18] = (uint32_t (*)[128][18])(smraw + 36864);
    const int tid = threadIdx.x;
    const int m0 = blockIdx.x * 128;
    const int wid = tid >> 5, lane = tid & 31;
    const int wm0 = (wid & 1) * 64, wn0 = (wid >> 1) * 32;
    const int gr = lane >> 2, cp = lane & 3;
    float acc[4][4][4] = {};
    const int lrow = tid >> 1, lhalf = tid & 1;
    const float* Yf = g_ydir[0];
    const float* Yb = g_ydir[1];
    for (int k0 = 0; k0 < DI; k0 += 32) {
        {
            const float4* pf = (const float4*)&Yf[(size_t)(m0 + lrow) * DI + k0 + lhalf * 16];
            const float4* pb = (const float4*)&Yb[(size_t)(m0 + lrow) * DI + k0 + lhalf * 16];
            float v[16];
#pragma unroll
            for (int q = 0; q < 4; q++) {
                float4 a = pf[q], bq = pb[q];
                v[q*4+0] = a.x + bq.x; v[q*4+1] = a.y + bq.y;
                v[q*4+2] = a.z + bq.z; v[q*4+3] = a.w + bq.w;
            }
            uint32_t* dh = &As[0][lrow][lhalf * 8];
            uint32_t* dl = &As[1][lrow][lhalf * 8];
#pragma unroll
            for (int q = 0; q < 8; q++) {
                __nv_bfloat16 h0, l0, h1, l1;
                bsplit(v[2*q], h0, l0);
                bsplit(v[2*q+1], h1, l1);
                dh[q] = pack2(h0, h1);
                dl[q] = pack2(l0, l1);
            }
        }
#pragma unroll
        for (int sel = 0; sel < 2; sel++) {
            const __nv_bfloat16* src = sel ? g_wol : g_woh;
            const uint4* gp = (const uint4*)&src[(size_t)lrow * DI + k0 + lhalf * 16];
            uint4 v0 = gp[0], v1 = gp[1];
            uint32_t* d = &Bs[sel][lrow][lhalf * 8];
            d[0] = v0.x; d[1] = v0.y; d[2] = v0.z; d[3] = v0.w;
            d[4] = v1.x; d[5] = v1.y; d[6] = v1.z; d[7] = v1.w;
        }
        __syncthreads();
#pragma unroll
        for (int pass = 0; pass < 3; pass++) {
            uint32_t (*pA)[18] = As[pass == 2 ? 1 : 0];
            uint32_t (*pB)[18] = Bs[pass == 1 ? 1 : 0];
#pragma unroll
            for (int k16 = 0; k16 < 2; k16++) {
                const int kp = k16 * 8;
                uint32_t a[4][4], bf[4][2];
#pragma unroll
                for (int i = 0; i < 4; i++) {
                    int rbase = wm0 + 16 * i;
                    a[i][0] = pA[rbase + gr][kp + cp];
                    a[i][1] = pA[rbase + gr + 8][kp + cp];
                    a[i][2] = pA[rbase + gr][kp + cp + 4];
                    a[i][3] = pA[rbase + gr + 8][kp + cp + 4];
                }
#pragma unroll
                for (int j = 0; j < 4; j++) {
                    int brow = wn0 + 8 * j + gr;
                    bf[j][0] = pB[brow][kp + cp];
                    bf[j][1] = pB[brow][kp + cp + 4];
                }
#pragma unroll
                for (int i = 0; i < 4; i++)
#pragma unroll
                    for (int j = 0; j < 4; j++)
                        mma16816(acc[i][j], a[i], bf[j]);
            }
        }
        __syncthreads();
    }
    // ---- epilogue: acc -> smem, + residual, LN over channels, write out ----
    float (*sD)[129] = (float (*)[129])smraw;
    float (*prs)[2] = (float (*)[2])(smraw + 66048);
    float (*prq)[2] = (float (*)[2])(smraw + 67072);
    float* mu   = (float*)(smraw + 68096);
    float* rstd = (float*)(smraw + 68608);
#pragma unroll
    for (int i = 0; i < 4; i++) {
#pragma unroll
        for (int j = 0; j < 4; j++) {
            int row = wm0 + 16 * i + gr;
            int col = wn0 + 8 * j + cp * 2;
            sD[row][col]     = acc[i][j][0];
            sD[row][col + 1] = acc[i][j][1];
            sD[row + 8][col]     = acc[i][j][2];
            sD[row + 8][col + 1] = acc[i][j][3];
        }
    }
    __syncthreads();
    const int b  = m0 / LL;
    const int l0 = m0 % LL;
#pragma unroll
    for (int i = 0; i < 64; i++) {
        int e = tid + i * 256;
        int l = e & 127, c = e >> 7;
        sD[l][c] += x[(size_t)(b * DM + c) * LL + l0 + l];
    }
    __syncthreads();
    {
        int r = tid >> 1, half = tid & 1;
        float su = 0.f, sq = 0.f;
#pragma unroll
        for (int cc = 0; cc < 64; cc++) {
            float v = sD[r][half * 64 + cc];
            su += v; sq = fmaf(v, v, sq);
        }
        prs[r][half] = su; prq[r][half] = sq;
    }
    __syncthreads();
    if (tid < 128) {
        float su = prs[tid][0] + prs[tid][1];
        float sq = prq[tid][0] + prq[tid][1];
        float m = su * (1.f / DM);
        float var = sq * (1.f / DM) - m * m;
        mu[tid] = m; rstd[tid] = rsqrtf(var + 1e-5f);
    }
    __syncthreads();
#pragma unroll
    for (int i = 0; i < 64; i++) {
        int e = tid + i * 256;
        int l = e & 127, c = e >> 7;
        out[(size_t)(b * DM + c) * LL + l0 + l] =
            (sD[l][c] - mu[l]) * rstd[l] * lw[c] + lb[c];
    }
}

// ------------------------- scan pass 1 (inline dt) --------------------------
__global__ void k_scan1(const float* __restrict__ Alog_f, const float* __restrict__ Alog_b,
                        const float* __restrict__ dtw_f, const float* __restrict__ dtb_f,
                        const float* __restrict__ dtw_b, const float* __restrict__ dtb_b) {
    int ch = blockIdx.x, b = blockIdx.y, dir = blockIdx.z, d = threadIdx.x;
    const float* Alog = dir ? Alog_b : Alog_f;
    const float* dtw  = dir ? dtw_b : dtw_f;
    float dtb = (dir ? dtb_b : dtb_f)[d];
    __shared__ __align__(16) float sd[CHUNK][24];
    int t0 = ch * CHUNK;
    const float* gsrc = g_dbl[dir] + (size_t)(b * LL + t0) * NDBL;
    for (int i = threadIdx.x; i < CHUNK * 6; i += 256) {
        int t = i / 6, q = i - t * 6;
        *((float4*)&sd[t][q * 4]) = *((const float4*)&gsrc[t * NDBL + q * 4]);
    }
    float Ad[NS], h[NS], wdt[DTR];
    bool fast = true;
#pragma unroll
    for (int n = 0; n < NS; n++) {
        Ad[n] = -__expf(Alog[d * NS + n]);
        fast = fast && (fabsf(Ad[n] + (float)(n + 1)) <= 1e-5f * (n + 1));
    }
#pragma unroll
    for (int i = 0; i < DTR; i++) wdt[i] = dtw[d * DTR + i];
#pragma unroll
    for (int n = 0; n < NS; n++) h[n] = 0.f;
    const uint32_t* xc = g_xc32[dir] + (size_t)(b * LL + t0) * DI + d;
    float rP = 1.f, S = 0.f;
    __syncthreads();
    if (fast) {
#pragma unroll 2
        for (int t = 0; t < CHUNK; t++) {
            const float* row = sd[t];
            float4 d0 = *(const float4*)&row[0];
            float4 d1 = *(const float4*)&row[4];
            float a = dtb;
            a = fmaf(wdt[0], d0.x, a); a = fmaf(wdt[1], d0.y, a);
            a = fmaf(wdt[2], d0.z, a); a = fmaf(wdt[3], d0.w, a);
            a = fmaf(wdt[4], d1.x, a); a = fmaf(wdt[5], d1.y, a);
            a = fmaf(wdt[6], d1.z, a); a = fmaf(wdt[7], d1.w, a);
            float r, dt; dt_math(a, r, dt);
            float cB = dt * unpack_sum(xc[(size_t)t * DI]);
            float4 B0 = *(const float4*)&row[8],  B1 = *(const float4*)&row[12];
            float4 B2 = *(const float4*)&row[16], B3 = *(const float4*)&row[20];
            float Bv[16] = {B0.x,B0.y,B0.z,B0.w, B1.x,B1.y,B1.z,B1.w,
                            B2.x,B2.y,B2.z,B2.w, B3.x,B3.y,B3.z,B3.w};
            float wv[NS];
            mkpow(r, wv);
            rP *= r;
#pragma unroll
            for (int n = 0; n < NS; n++)
                h[n] = fmaf(wv[n], h[n], cB * Bv[n]);
        }
    } else {
        for (int t = 0; t < CHUNK; t++) {
            const float* row = sd[t];
            float a = dtb;
#pragma unroll
            for (int i = 0; i < DTR; i++) a = fmaf(wdt[i], row[i], a);
            float r, dt; dt_math(a, r, dt);
            float cB = dt * unpack_sum(xc[(size_t)t * DI]);
            S += dt;
#pragma unroll
            for (int n = 0; n < NS; n++)
                h[n] = fmaf(__expf(dt * Ad[n]), h[n], cB * row[8 + n]);
        }
    }
    int base = ((dir * NCH + ch) * BB + b) * NS;
    if (fast) {
        float pw[NS];
        mkpow(rP, pw);
#pragma unroll
        for (int n = 0; n < NS; n++) {
            g_hend[(base + n) * DI + d] = h[n];
            g_P[(base + n) * DI + d]    = pw[n];
        }
    } else {
#pragma unroll
        for (int n = 0; n < NS; n++) {
            g_hend[(base + n) * DI + d] = h[n];
            g_P[(base + n) * DI + d]    = __expf(Ad[n] * S);
        }
    }
}

// ------------------------- scan pass 2 --------------------------------------
__global__ void k_scan2() {
    int d = threadIdx.x;
    int n   = blockIdx.x & 15;
    int b   = (blockIdx.x >> 4) & 3;
    int dir = blockIdx.x >> 6;
    float hs = 0.f;
    for (int ch = 0; ch < NCH; ch++) {
        int idx = (((dir * NCH + ch) * BB + b) * NS + n) * DI + d;
        g_hinit[idx] = hs;
        hs = fmaf(g_P[idx], hs, g_hend[idx]);
    }
}

// ------------------------- scan pass 3 (inline dt, emit y) ------------------
__global__ void k_scan3(const float* __restrict__ Alog_f, const float* __restrict__ Dsk_f,
                        const float* __restrict__ Alog_b, const float* __restrict__ Dsk_b,
                        const float* __restrict__ dtw_f, const float* __restrict__ dtb_f,
                        const float* __restrict__ dtw_b, const float* __restrict__ dtb_b) {
    int ch = blockIdx.x, b = blockIdx.y, dir = blockIdx.z, d = threadIdx.x;
    const float* Alog = dir ? Alog_b : Alog_f;
    const float* dtw  = dir ? dtw_b : dtw_f;
    float dtb = (dir ? dtb_b : dtb_f)[d];
    float Dd  = (dir ? Dsk_b : Dsk_f)[d];
    __shared__ __align__(16) float sd[CHUNK][40];
    int t0 = ch * CHUNK;
    const float* gsrc = g_dbl[dir] + (size_t)(b * LL + t0) * NDBL;
    for (int i = threadIdx.x; i < CHUNK * 10; i += 256) {
        int t = i / 10, q = i - t * 10;
        *((float4*)&sd[t][q * 4]) = *((const float4*)&gsrc[t * NDBL + q * 4]);
    }
    float Ad[NS], h[NS], wdt[DTR];
    bool fast = true;
#pragma unroll
    for (int n = 0; n < NS; n++) {
        Ad[n] = -__expf(Alog[d * NS + n]);
        fast = fast && (fabsf(Ad[n] + (float)(n + 1)) <= 1e-5f * (n + 1));
    }
#pragma unroll
    for (int i = 0; i < DTR; i++) wdt[i] = dtw[d * DTR + i];
    int base = ((dir * NCH + ch) * BB + b) * NS;
#pragma unroll
    for (int n = 0; n < NS; n++) h[n] = g_hinit[(base + n) * DI + d];
    const uint32_t* xc = g_xc32[dir] + (size_t)(b * LL + t0) * DI + d;
    const float* xzz = g_xz + (size_t)b * LL * 512 + DI + d;   // pre-gated silu(z)
    float* yout = g_ydir[dir] + (size_t)b * LL * DI + d;
    __syncthreads();
    if (fast) {
#pragma unroll 2
        for (int t = 0; t < CHUNK; t++) {
            const float* row = sd[t];
            float4 d0 = *(const float4*)&row[0];
            float4 d1 = *(const float4*)&row[4];
            float a = dtb;
            a = fmaf(wdt[0], d0.x, a); a = fmaf(wdt[1], d0.y, a);
            a = fmaf(wdt[2], d0.z, a); a = fmaf(wdt[3], d0.w, a);
            a = fmaf(wdt[4], d1.x, a); a = fmaf(wdt[5], d1.y, a);
            a = fmaf(wdt[6], d1.z, a); a = fmaf(wdt[7], d1.w, a);
            float r, dt; dt_math(a, r, dt);
            float xv = unpack_sum(xc[(size_t)t * DI]);
            float cB = dt * xv;
            float4 B0 = *(const float4*)&row[8],  B1 = *(const float4*)&row[12];
            float4 B2 = *(const float4*)&row[16], B3 = *(const float4*)&row[20];
            float4 C0 = *(const float4*)&row[24], C1 = *(const float4*)&row[28];
            float4 C2 = *(const float4*)&row[32], C3 = *(const float4*)&row[36];
            float Bv[16] = {B0.x,B0.y,B0.z,B0.w, B1.x,B1.y,B1.z,B1.w,
                            B2.x,B2.y,B2.z,B2.w, B3.x,B3.y,B3.z,B3.w};
            float Cv[16] = {C0.x,C0.y,C0.z,C0.w, C1.x,C1.y,C1.z,C1.w,
                            C2.x,C2.y,C2.z,C2.w, C3.x,C3.y,C3.z,C3.w};
            float wv[NS];
            mkpow(r, wv);
            float y = 0.f;
#pragma unroll
            for (int n = 0; n < NS; n++) {
                h[n] = fmaf(wv[n], h[n], cB * Bv[n]);
                y = fmaf(h[n], Cv[n], y);
            }
            int torig = dir ? (LL - 1 - (t0 + t)) : (t0 + t);
            float zg = xzz[(size_t)torig * 512];
            yout[(size_t)torig * DI] = (y + xv * Dd) * zg;
        }
    } else {
        for (int t = 0; t < CHUNK; t++) {
            const float* row = sd[t];
            float a = dtb;
#pragma unroll
            for (int i = 0; i < DTR; i++) a = fmaf(wdt[i], row[i], a);
            float r, dt; dt_math(a, r, dt);
            float xv = unpack_sum(xc[(size_t)t * DI]);
            float cB = dt * xv;
            float y = 0.f;
#pragma unroll
            for (int n = 0; n < NS; n++) {
                h[n] = fmaf(__expf(dt * Ad[n]), h[n], cB * row[8 + n]);
                y = fmaf(h[n], row[24 + n], y);
            }
            int torig = dir ? (LL - 1 - (t0 + t)) : (t0 + t);
            float zg = xzz[(size_t)torig * 512];
            yout[(size_t)torig * DI] = (y + xv * Dd) * zg;
        }
    }
}

// ------------------------- launch ------------------------------------------
extern "C" void kernel_launch(void* const* d_in, const int* in_sizes, int n_in,
                              void* d_out, int out_size) {
    const float* x        = (const float*)d_in[0];
    const float* ln1_w    = (const float*)d_in[1];
    const float* ln1_b    = (const float*)d_in[2];
    const float* ln2_w    = (const float*)d_in[3];
    const float* ln2_b    = (const float*)d_in[4];
    const float* in_proj  = (const float*)d_in[5];
    const float* out_proj = (const float*)d_in[6];
    const float* conv_w_f = (const float*)d_in[7];
    const float* conv_b_f = (const float*)d_in[8];
    const float* xproj_f  = (const float*)d_in[9];
    const float* dtw_f    = (const float*)d_in[10];
    const float* dtb_f    = (const float*)d_in[11];
    const float* Alog_f   = (const float*)d_in[12];
    const float* D_f      = (const float*)d_in[13];
    const float* conv_w_b = (const float*)d_in[14];
    const float* conv_b_b = (const float*)d_in[15];
    const float* xproj_b  = (const float*)d_in[16];
    const float* dtw_b    = (const float*)d_in[17];
    const float* dtb_b    = (const float*)d_in[18];
    const float* Alog_b   = (const float*)d_in[19];
    const float* D_b      = (const float*)d_in[20];
    float* out = (float*)d_out;

    static bool attr_done = false;
    if (!attr_done) {
        cudaFuncSetAttribute(gemm_out, cudaFuncAttributeMaxDynamicSharedMemorySize, OUT_SMEM);
        cudaFuncSetAttribute(gemm_in_ln, cudaFuncAttributeMaxDynamicSharedMemorySize, IN_SMEM);
        attr_done = true;
    }

    float *p_xz, *p_dbl;
    __nv_bfloat16 *p_xpwh, *p_xpwl;
    uint32_t *p_xc32;
    cudaGetSymbolAddress((void**)&p_xz,   g_xz);
    cudaGetSymbolAddress((void**)&p_dbl,  g_dbl);
    cudaGetSymbolAddress((void**)&p_xpwh, g_xpwh);
    cudaGetSymbolAddress((void**)&p_xpwl, g_xpwl);
    cudaGetSymbolAddress((void**)&p_xc32, g_xc32);

    // 0. weight bf16 splits
    int wtot = 512 * 128 + 128 * 256 + 2 * 64 * 256;
    k_wconv<<<(wtot + 255) / 256, 256>>>(in_proj, out_proj, xproj_f, xproj_b);

    // 1. in_proj with fused LN1 (z half silu-gated): -> g_xz
    gemm_in_ln<<<dim3(MTOK / 128, 4), 256, IN_SMEM>>>(x, ln1_w, ln1_b, p_xz);

    // 2. conv + silu + packed split, both dirs
    k_conv2<<<dim3(LL / 16, BB), 256>>>(conv_w_f, conv_b_f, conv_w_b, conv_b_b);

    // 3. x_proj per dir (BN=64, packed A): -> g_dbl
    gemm_xp<DI, 64><<<dim3(MTOK / 128, 1), 256>>>(
        p_xc32, p_xpwh, p_xpwl, p_dbl, NDBL);
    gemm_xp<DI, 64><<<dim3(MTOK / 128, 1), 256>>>(
        p_xc32 + (size_t)MTOK * DI,
        p_xpwh + (size_t)64 * 256, p_xpwl + (size_t)64 * 256,
        p_dbl + (size_t)MTOK * NDBL, NDBL);

    // 4-6. chunked selective scan (dt inline)
    k_scan1<<<dim3(NCH, BB, 2), 256>>>(Alog_f, Alog_b, dtw_f, dtb_f, dtw_b, dtb_b);
    k_scan2<<<2 * BB * NS, 256>>>();
    k_scan3<<<dim3(NCH, BB, 2), 256>>>(Alog_f, D_f, Alog_b, D_b,
                                       dtw_f, dtb_f, dtw_b, dtb_b);

    // 7. out_proj + residual + LN2 -> final output
    gemm_out<<<dim3(MTOK / 128, 1), 256, OUT_SMEM>>>(x, ln2_w, ln2_b, out);
}

// round 15
// speedup vs baseline: 1.1050x; 1.0075x over previous
#include <cuda_runtime.h>
#include <cuda_bf16.h>
#include <cstdint>

// ---------------------------------------------------------------------------
// MambaLayer (bidirectional VideoMamba), B200 sm_100 — round 15
// f32x2-packed scan inner loops; merged dual-direction xproj launch
// ---------------------------------------------------------------------------

#define BB   4
#define DM   128
#define LL   8192
#define DI   256
#define NS   16
#define DTR  8
#define NDBL 40
#define MTOK (BB*LL)
#define CHUNK 64
#define NCH  (LL/CHUNK)
#define OUT_SMEM 73728
#define IN_SMEM  104960

// ------------------------- scratch (static device mem) ---------------------
__device__ float          g_xz    [MTOK*2*DI];      // z half pre-gated by silu
__device__ float          g_dbl   [2][MTOK*NDBL];
__device__ uint32_t       g_xc32  [2][MTOK*DI];     // packed bf16 (hi | lo<<16)
__device__ float          g_ydir  [2][MTOK*DI];
__device__ float          g_hend  [2*NCH*BB*NS*DI];
__device__ float          g_P     [2*NCH*BB*NS*DI];
__device__ float          g_hinit [2*NCH*BB*NS*DI];
__device__ __nv_bfloat16  g_wih[512*128],  g_wil[512*128];
__device__ __nv_bfloat16  g_woh[128*256],  g_wol[128*256];
__device__ __nv_bfloat16  g_xpwh[2][64*256], g_xpwl[2][64*256]; // rows>=40 zero

// ------------------------- math helpers -------------------------------------
__device__ __forceinline__ float siluf(float x) {
    return __fdividef(x, 1.f + __expf(-x));
}
__device__ __forceinline__ void mkpow(float r, float* w) {
    float r2 = r * r, r3 = r2 * r, r4 = r2 * r2;
    float r5 = r4 * r, r6 = r4 * r2, r7 = r4 * r3, r8 = r4 * r4;
    w[0]=r;  w[1]=r2; w[2]=r3; w[3]=r4; w[4]=r5; w[5]=r6; w[6]=r7; w[7]=r8;
    w[8]=r8*r; w[9]=r8*r2; w[10]=r8*r3; w[11]=r8*r4;
    w[12]=r8*r5; w[13]=r8*r6; w[14]=r8*r7; w[15]=r8*r8;
}
__device__ __forceinline__ void bsplit(float v, __nv_bfloat16& hi, __nv_bfloat16& lo) {
    hi = __float2bfloat16(v);
    lo = __float2bfloat16(v - __bfloat162float(hi));
}
__device__ __forceinline__ uint32_t pack2(__nv_bfloat16 a, __nv_bfloat16 b) {
    return (uint32_t)__bfloat16_as_ushort(a) | ((uint32_t)__bfloat16_as_ushort(b) << 16);
}
__device__ __forceinline__ float unpack_sum(uint32_t p) {
    __nv_bfloat16 h = __ushort_as_bfloat16((unsigned short)(p & 0xffffu));
    __nv_bfloat16 l = __ushort_as_bfloat16((unsigned short)(p >> 16));
    return __bfloat162float(h) + __bfloat162float(l);
}
__device__ __forceinline__ void dt_math(float a, float& r, float& dt) {
    float e = __expf(a);
    r = __fdividef(1.f, 1.f + e);
    if (a > 15.f)      dt = a;
    else if (a > -3.f) dt = __logf(1.f + e);
    else               dt = e * fmaf(e, fmaf(e, 0.33333334f, -0.5f), 1.f);
}
__device__ __forceinline__ void mma16816(float* c, const uint32_t* a, const uint32_t* b) {
    asm volatile(
        "mma.sync.aligned.m16n8k16.row.col.f32.bf16.bf16.f32 "
        "{%0,%1,%2,%3}, {%4,%5,%6,%7}, {%8,%9}, {%0,%1,%2,%3};"
        : "+f"(c[0]), "+f"(c[1]), "+f"(c[2]), "+f"(c[3])
        : "r"(a[0]), "r"(a[1]), "r"(a[2]), "r"(a[3]), "r"(b[0]), "r"(b[1]));
}
// ---- packed f32x2 (Blackwell base ISA) ----
__device__ __forceinline__ unsigned long long pkf2(float lo, float hi) {
    unsigned long long r;
    asm("mov.b64 %0, {%1, %2};" : "=l"(r) : "f"(lo), "f"(hi));
    return r;
}
__device__ __forceinline__ void upkf2(unsigned long long p, float& lo, float& hi) {
    asm("mov.b64 {%0, %1}, %2;" : "=f"(lo), "=f"(hi) : "l"(p));
}
#define FMAX2(d, a, b, c) asm("fma.rn.f32x2 %0, %1, %2, %3;" : "=l"(d) : "l"(a), "l"(b), "l"(c))
#define MULX2(d, a, b)    asm("mul.rn.f32x2 %0, %1, %2;" : "=l"(d) : "l"(a), "l"(b))

// ------------------------- weight convert -----------------------------------
__global__ void k_wconv(const float* __restrict__ wi, const float* __restrict__ wo,
                        const float* __restrict__ xpf, const float* __restrict__ xpb) {
    int i = blockIdx.x * 256 + threadIdx.x;
    if (i < 512 * 128) { bsplit(wi[i], g_wih[i], g_wil[i]); return; }
    int j = i - 512 * 128;
    if (j < 128 * 256) { bsplit(wo[j], g_woh[j], g_wol[j]); return; }
    int k = j - 128 * 256;
    if (k < 2 * 64 * 256) {
        int dir = k / (64 * 256);
        int idx = k - dir * 64 * 256;
        int n = idx >> 8;
        const float* src = dir ? xpb : xpf;
        float v = (n < NDBL) ? src[idx] : 0.f;
        bsplit(v, g_xpwh[dir][idx], g_xpwl[dir][idx]);
    }
}

// ------------------------- in_proj GEMM with fused LN1 ----------------------
__global__ __launch_bounds__(256) void gemm_in_ln(
        const float* __restrict__ x,
        const float* __restrict__ lw, const float* __restrict__ lb,
        float* __restrict__ C) {
    extern __shared__ __align__(16) char smraw[];
    float (*xn)[133] = (float (*)[133])smraw;
    uint32_t (*As)[128][18] = (uint32_t (*)[128][18])(smraw + 68096);
    uint32_t (*Bs)[128][18] = (uint32_t (*)[128][18])(smraw + 68096 + 18432);
    __shared__ float prs[128][2], prq[128][2], mu[128], rstd[128];
    const int tid = threadIdx.x;
    const int m0 = blockIdx.x * 128, n0 = blockIdx.y * 128;
    const int b = m0 / LL, l0 = m0 % LL;
#pragma unroll
    for (int i = 0; i < 64; i++) {
        int e = tid + i * 256;
        int l = e & 127, c = e >> 7;
        xn[l][c] = x[(size_t)(b * DM + c) * LL + l0 + l];
    }
    __syncthreads();
    {
        int r = tid >> 1, half = tid & 1;
        float su = 0.f, sq = 0.f;
#pragma unroll
        for (int cc = 0; cc < 64; cc++) {
            float v = xn[r][half * 64 + cc];
            su += v; sq = fmaf(v, v, sq);
        }
        prs[r][half] = su; prq[r][half] = sq;
    }
    __syncthreads();
    if (tid < 128) {
        float su = prs[tid][0] + prs[tid][1];
        float sq = prq[tid][0] + prq[tid][1];
        float m = su * (1.f / DM);
        float var = sq * (1.f / DM) - m * m;
        mu[tid] = m; rstd[tid] = rsqrtf(var + 1e-5f);
    }
    __syncthreads();
    const int wid = tid >> 5, lane = tid & 31;
    const int wm0 = (wid & 1) * 64, wn0 = (wid >> 1) * 32;
    const int gr = lane >> 2, cp = lane & 3;
    float acc[4][4][4] = {};
    const int lrow = tid >> 1, lhalf = tid & 1;
    const float mm = mu[lrow], ms = rstd[lrow];
    for (int k0 = 0; k0 < DM; k0 += 32) {
        {
            const int c0 = k0 + lhalf * 16;
            uint32_t* dh = &As[0][lrow][lhalf * 8];
            uint32_t* dl = &As[1][lrow][lhalf * 8];
#pragma unroll
            for (int q = 0; q < 8; q++) {
                int c = c0 + q * 2;
                float v0 = (xn[lrow][c]     - mm) * ms * lw[c]     + lb[c];
                float v1 = (xn[lrow][c + 1] - mm) * ms * lw[c + 1] + lb[c + 1];
                __nv_bfloat16 h0, lo0, h1, lo1;
                bsplit(v0, h0, lo0);
                bsplit(v1, h1, lo1);
                dh[q] = pack2(h0, h1);
                dl[q] = pack2(lo0, lo1);
            }
        }
#pragma unroll
        for (int sel = 0; sel < 2; sel++) {
            const __nv_bfloat16* src = sel ? g_wil : g_wih;
            const uint4* gp = (const uint4*)&src[(size_t)(n0 + lrow) * DM + k0 + lhalf * 16];
            uint4 v0 = gp[0], v1 = gp[1];
            uint32_t* d = &Bs[sel][lrow][lhalf * 8];
            d[0] = v0.x; d[1] = v0.y; d[2] = v0.z; d[3] = v0.w;
            d[4] = v1.x; d[5] = v1.y; d[6] = v1.z; d[7] = v1.w;
        }
        __syncthreads();
#pragma unroll
        for (int pass = 0; pass < 3; pass++) {
            uint32_t (*pA)[18] = As[pass == 2 ? 1 : 0];
            uint32_t (*pB)[18] = Bs[pass == 1 ? 1 : 0];
#pragma unroll
            for (int k16 = 0; k16 < 2; k16++) {
                const int kp = k16 * 8;
                uint32_t a[4][4], bf[4][2];
#pragma unroll
                for (int i = 0; i < 4; i++) {
                    int rbase = wm0 + 16 * i;
                    a[i][0] = pA[rbase + gr][kp + cp];
                    a[i][1] = pA[rbase + gr + 8][kp + cp];
                    a[i][2] = pA[rbase + gr][kp + cp + 4];
                    a[i][3] = pA[rbase + gr + 8][kp + cp + 4];
                }
#pragma unroll
                for (int j = 0; j < 4; j++) {
                    int brow = wn0 + 8 * j + gr;
                    bf[j][0] = pB[brow][kp + cp];
                    bf[j][1] = pB[brow][kp + cp + 4];
                }
#pragma unroll
                for (int i = 0; i < 4; i++)
#pragma unroll
                    for (int j = 0; j < 4; j++)
                        mma16816(acc[i][j], a[i], bf[j]);
            }
        }
        __syncthreads();
    }
    const bool zh = (n0 >= 256);
#pragma unroll
    for (int i = 0; i < 4; i++) {
#pragma unroll
        for (int j = 0; j < 4; j++) {
            int row = m0 + wm0 + 16 * i + gr;
            int col = n0 + wn0 + 8 * j + cp * 2;
            float2 c0 = make_float2(acc[i][j][0], acc[i][j][1]);
            float2 c1 = make_float2(acc[i][j][2], acc[i][j][3]);
            if (zh) {
                c0.x = siluf(c0.x); c0.y = siluf(c0.y);
                c1.x = siluf(c1.x); c1.y = siluf(c1.y);
            }
            *(float2*)&C[(size_t)row * 512 + col] = c0;
            *(float2*)&C[(size_t)(row + 8) * 512 + col] = c1;
        }
    }
}

// ------------------------- x_proj GEMM (packed A, BN=64, both dirs) ---------
__global__ __launch_bounds__(256) void gemm_xp(float* __restrict__ Cbase) {
    __shared__ uint32_t As[2][128][18];
    __shared__ uint32_t Bs[2][64][18];
    const int tid = threadIdx.x;
    const int dir = blockIdx.y;
    const int m0 = blockIdx.x * 128;
    const uint32_t* A1 = g_xc32[dir];
    const __nv_bfloat16* Bh = g_xpwh[dir];
    const __nv_bfloat16* Bl = g_xpwl[dir];
    float* C = Cbase + (size_t)dir * MTOK * NDBL;
    const int wid = tid >> 5, lane = tid & 31;
    const int wm0 = (wid & 3) * 32, wn0 = (wid >> 2) * 32;
    const int gr = lane >> 2, cp = lane & 3;
    float acc[2][4][4] = {};
    const int lrow = tid >> 1, lhalf = tid & 1;
    for (int k0 = 0; k0 < DI; k0 += 32) {
        {
            const uint4* gp = (const uint4*)&A1[(size_t)(m0 + lrow) * DI + k0 + lhalf * 16];
            uint4 p0 = gp[0], p1 = gp[1], p2 = gp[2], p3 = gp[3];
            uint32_t pw[16] = {p0.x,p0.y,p0.z,p0.w, p1.x,p1.y,p1.z,p1.w,
                               p2.x,p2.y,p2.z,p2.w, p3.x,p3.y,p3.z,p3.w};
            uint32_t* dh = &As[0][lrow][lhalf * 8];
            uint32_t* dl = &As[1][lrow][lhalf * 8];
#pragma unroll
            for (int q = 0; q < 8; q++) {
                dh[q] = __byte_perm(pw[2*q], pw[2*q+1], 0x5410);
                dl[q] = __byte_perm(pw[2*q], pw[2*q+1], 0x7632);
            }
        }
        if (tid < 128) {
#pragma unroll
            for (int sel = 0; sel < 2; sel++) {
                const __nv_bfloat16* src = sel ? Bl : Bh;
                const uint4* gp = (const uint4*)&src[(size_t)lrow * DI + k0 + lhalf * 16];
                uint4 v0 = gp[0], v1 = gp[1];
                uint32_t* d = &Bs[sel][lrow][lhalf * 8];
                d[0] = v0.x; d[1] = v0.y; d[2] = v0.z; d[3] = v0.w;
                d[4] = v1.x; d[5] = v1.y; d[6] = v1.z; d[7] = v1.w;
            }
        }
        __syncthreads();
#pragma unroll
        for (int pass = 0; pass < 3; pass++) {
            uint32_t (*pA)[18] = As[pass == 2 ? 1 : 0];
            uint32_t (*pB)[18] = Bs[pass == 1 ? 1 : 0];
#pragma unroll
            for (int k16 = 0; k16 < 2; k16++) {
                const int kp = k16 * 8;
                uint32_t a[2][4], bf[4][2];
#pragma unroll
                for (int i = 0; i < 2; i++) {
                    int rbase = wm0 + 16 * i;
                    a[i][0] = pA[rbase + gr][kp + cp];
                    a[i][1] = pA[rbase + gr + 8][kp + cp];
                    a[i][2] = pA[rbase + gr][kp + cp + 4];
                    a[i][3] = pA[rbase + gr + 8][kp + cp + 4];
                }
#pragma unroll
                for (int j = 0; j < 4; j++) {
                    int brow = wn0 + 8 * j + gr;
                    bf[j][0] = pB[brow][kp + cp];
                    bf[j][1] = pB[brow][kp + cp + 4];
                }
#pragma unroll
                for (int i = 0; i < 2; i++)
#pragma unroll
                    for (int j = 0; j < 4; j++)
                        mma16816(acc[i][j], a[i], bf[j]);
            }
        }
        __syncthreads();
    }
#pragma unroll
    for (int i = 0; i < 2; i++) {
#pragma unroll
        for (int j = 0; j < 4; j++) {
            int row = m0 + wm0 + 16 * i + gr;
            int col = wn0 + 8 * j + cp * 2;
            if (col < NDBL) {
                *(float2*)&C[(size_t)row * NDBL + col] = make_float2(acc[i][j][0], acc[i][j][1]);
                *(float2*)&C[(size_t)(row + 8) * NDBL + col] = make_float2(acc[i][j][2], acc[i][j][3]);
            }
        }
    }
}

// ------------------------- conv + silu + packed split, BOTH dirs ------------
__global__ void k_conv2(const float* __restrict__ cwf, const float* __restrict__ cbf,
                        const float* __restrict__ cwb, const float* __restrict__ cbb) {
    int d = threadIdx.x;
    int t0 = blockIdx.x * 16;
    int b = blockIdx.y;
    float wf0 = cwf[d*4], wf1 = cwf[d*4+1], wf2 = cwf[d*4+2], wf3 = cwf[d*4+3];
    float bf = cbf[d];
    float wb0 = cwb[d*4], wb1 = cwb[d*4+1], wb2 = cwb[d*4+2], wb3 = cwb[d*4+3];
    float bb = cbb[d];
    const float* xp = g_xz + (size_t)(b * LL) * 512 + d;
    float v[7];
    const bool edge = (blockIdx.x == 0) || (blockIdx.x == gridDim.x - 1);
    if (edge) {
#pragma unroll
        for (int j = 0; j < 7; j++) {
            int tt = t0 - 3 + j;
            v[j] = (tt >= 0 && tt < LL) ? xp[(size_t)tt * 512] : 0.f;
        }
#pragma unroll
        for (int i = 0; i < 16; i++) {
            int t = t0 + i;
            float f  = bf + wf0*v[0] + wf1*v[1] + wf2*v[2] + wf3*v[3];
            float bw = bb + wb0*v[6] + wb1*v[5] + wb2*v[4] + wb3*v[3];
            __nv_bfloat16 h, l;
            bsplit(siluf(f), h, l);
            g_xc32[0][(size_t)(b * LL + t) * DI + d] = pack2(h, l);
            bsplit(siluf(bw), h, l);
            g_xc32[1][(size_t)(b * LL + (LL - 1 - t)) * DI + d] = pack2(h, l);
            v[0]=v[1]; v[1]=v[2]; v[2]=v[3]; v[3]=v[4]; v[4]=v[5]; v[5]=v[6];
            int tn = t + 4;
            v[6] = (tn < LL) ? xp[(size_t)tn * 512] : 0.f;
        }
    } else {
#pragma unroll
        for (int j = 0; j < 7; j++)
            v[j] = xp[(size_t)(t0 - 3 + j) * 512];
#pragma unroll
        for (int i = 0; i < 16; i++) {
            int t = t0 + i;
            float f  = bf + wf0*v[0] + wf1*v[1] + wf2*v[2] + wf3*v[3];
            float bw = bb + wb0*v[6] + wb1*v[5] + wb2*v[4] + wb3*v[3];
            __nv_bfloat16 h, l;
            bsplit(siluf(f), h, l);
            g_xc32[0][(size_t)(b * LL + t) * DI + d] = pack2(h, l);
            bsplit(siluf(bw), h, l);
            g_xc32[1][(size_t)(b * LL + (LL - 1 - t)) * DI + d] = pack2(h, l);
            v[0]=v[1]; v[1]=v[2]; v[2]=v[3]; v[3]=v[4]; v[4]=v[5]; v[5]=v[6];
            v[6] = xp[(size_t)(t + 4) * 512];
        }
    }
}

// ------------------------- out_proj GEMM + residual + LN2 -------------------
__global__ __launch_bounds__(256) void gemm_out(
        const float* __restrict__ x,
        const float* __restrict__ lw, const float* __restrict__ lb,
        float* __restrict__ out) {
    extern __shared__ __align__(16) char smraw[];
    uint32_t (*As)[128][18] = (uint32_t (*)[128][18])smraw;
    uint32_t (*Bs)[128][18] = (uint32_t (*)[128][18])(smraw + 36864);
    const int tid = threadIdx.x;
    const int m0 = blockIdx.x * 128;
    const int wid = tid >> 5, lane = tid & 31;
    const int wm0 = (wid & 1) * 64, wn0 = (wid >> 1) * 32;
    const int gr = lane >> 2, cp = lane & 3;
    float acc[4][4][4] = {};
    const int lrow = tid >> 1, lhalf = tid & 1;
    const float* Yf = g_ydir[0];
    const float* Yb = g_ydir[1];
    for (int k0 = 0; k0 < DI; k0 += 32) {
        {
            const float4* pf = (const float4*)&Yf[(size_t)(m0 + lrow) * DI + k0 + lhalf * 16];
            const float4* pb = (const float4*)&Yb[(size_t)(m0 + lrow) * DI + k0 + lhalf * 16];
            float v[16];
#pragma unroll
            for (int q = 0; q < 4; q++) {
                float4 a = pf[q], bq = pb[q];
                v[q*4+0] = a.x + bq.x; v[q*4+1] = a.y + bq.y;
                v[q*4+2] = a.z + bq.z; v[q*4+3] = a.w + bq.w;
            }
            uint32_t* dh = &As[0][lrow][lhalf * 8];
            uint32_t* dl = &As[1][lrow][lhalf * 8];
#pragma unroll
            for (int q = 0; q < 8; q++) {
                __nv_bfloat16 h0, l0, h1, l1;
                bsplit(v[2*q], h0, l0);
                bsplit(v[2*q+1], h1, l1);
                dh[q] = pack2(h0, h1);
                dl[q] = pack2(l0, l1);
            }
        }
#pragma unroll
        for (int sel = 0; sel < 2; sel++) {
            const __nv_bfloat16* src = sel ? g_wol : g_woh;
            const uint4* gp = (const uint4*)&src[(size_t)lrow * DI + k0 + lhalf * 16];
            uint4 v0 = gp[0], v1 = gp[1];
            uint32_t* d = &Bs[sel][lrow][lhalf * 8];
            d[0] = v0.x; d[1] = v0.y; d[2] = v0.z; d[3] = v0.w;
            d[4] = v1.x; d[5] = v1.y; d[6] = v1.z; d[7] = v1.w;
        }
        __syncthreads();
#pragma unroll
        for (int pass = 0; pass < 3; pass++) {
            uint32_t (*pA)[18] = As[pass == 2 ? 1 : 0];
            uint32_t (*pB)[18] = Bs[pass == 1 ? 1 : 0];
#pragma unroll
            for (int k16 = 0; k16 < 2; k16++) {
                const int kp = k16 * 8;
                uint32_t a[4][4], bf[4][2];
#pragma unroll
                for (int i = 0; i < 4; i++) {
                    int rbase = wm0 + 16 * i;
                    a[i][0] = pA[rbase + gr][kp + cp];
                    a[i][1] = pA[rbase + gr + 8][kp + cp];
                    a[i][2] = pA[rbase + gr][kp + cp + 4];
                    a[i][3] = pA[rbase + gr + 8][kp + cp + 4];
                }
#pragma unroll
                for (int j = 0; j < 4; j++) {
                    int brow = wn0 + 8 * j + gr;
                    bf[j][0] = pB[brow][kp + cp];
                    bf[j][1] = pB[brow][kp + cp + 4];
                }
#pragma unroll
                for (int i = 0; i < 4; i++)
#pragma unroll
                    for (int j = 0; j < 4; j++)
                        mma16816(acc[i][j], a[i], bf[j]);
            }
        }
        __syncthreads();
    }
    float (*sD)[129] = (float (*)[129])smraw;
    float (*prs)[2] = (float (*)[2])(smraw + 66048);
    float (*prq)[2] = (float (*)[2])(smraw + 67072);
    float* mu   = (float*)(smraw + 68096);
    float* rstd = (float*)(smraw + 68608);
#pragma unroll
    for (int i = 0; i < 4; i++) {
#pragma unroll
        for (int j = 0; j < 4; j++) {
            int row = wm0 + 16 * i + gr;
            int col = wn0 + 8 * j + cp * 2;
            sD[row][col]     = acc[i][j][0];
            sD[row][col + 1] = acc[i][j][1];
            sD[row + 8][col]     = acc[i][j][2];
            sD[row + 8][col + 1] = acc[i][j][3];
        }
    }
    __syncthreads();
    const int b  = m0 / LL;
    const int l0 = m0 % LL;
#pragma unroll
    for (int i = 0; i < 64; i++) {
        int e = tid + i * 256;
        int l = e & 127, c = e >> 7;
        sD[l][c] += x[(size_t)(b * DM + c) * LL + l0 + l];
    }
    __syncthreads();
    {
        int r = tid >> 1, half = tid & 1;
        float su = 0.f, sq = 0.f;
#pragma unroll
        for (int cc = 0; cc < 64; cc++) {
            float v = sD[r][half * 64 + cc];
            su += v; sq = fmaf(v, v, sq);
        }
        prs[r][half] = su; prq[r][half] = sq;
    }
    __syncthreads();
    if (tid < 128) {
        float su = prs[tid][0] + prs[tid][1];
        float sq = prq[tid][0] + prq[tid][1];
        float m = su * (1.f / DM);
        float var = sq * (1.f / DM) - m * m;
        mu[tid] = m; rstd[tid] = rsqrtf(var + 1e-5f);
    }
    __syncthreads();
#pragma unroll
    for (int i = 0; i < 64; i++) {
        int e = tid + i * 256;
        int l = e & 127, c = e >> 7;
        out[(size_t)(b * DM + c) * LL + l0 + l] =
            (sD[l][c] - mu[l]) * rstd[l] * lw[c] + lb[c];
    }
}

// ------------------------- scan pass 1 (packed f32x2 fast path) -------------
__global__ void k_scan1(const float* __restrict__ Alog_f, const float* __restrict__ Alog_b,
                        const float* __restrict__ dtw_f, const float* __restrict__ dtb_f,
                        const float* __restrict__ dtw_b, const float* __restrict__ dtb_b) {
    int ch = blockIdx.x, b = blockIdx.y, dir = blockIdx.z, d = threadIdx.x;
    const float* Alog = dir ? Alog_b : Alog_f;
    const float* dtw  = dir ? dtw_b : dtw_f;
    float dtb = (dir ? dtb_b : dtb_f)[d];
    __shared__ __align__(16) float sd[CHUNK][24];
    int t0 = ch * CHUNK;
    const float* gsrc = g_dbl[dir] + (size_t)(b * LL + t0) * NDBL;
    for (int i = threadIdx.x; i < CHUNK * 6; i += 256) {
        int t = i / 6, q = i - t * 6;
        *((float4*)&sd[t][q * 4]) = *((const float4*)&gsrc[t * NDBL + q * 4]);
    }
    float Ad[NS], wdt[DTR];
    bool fast = true;
#pragma unroll
    for (int n = 0; n < NS; n++) {
        Ad[n] = -__expf(Alog[d * NS + n]);
        fast = fast && (fabsf(Ad[n] + (float)(n + 1)) <= 1e-5f * (n + 1));
    }
#pragma unroll
    for (int i = 0; i < DTR; i++) wdt[i] = dtw[d * DTR + i];
    const uint32_t* xc = g_xc32[dir] + (size_t)(b * LL + t0) * DI + d;
    float rP = 1.f, S = 0.f;
    int base = ((dir * NCH + ch) * BB + b) * NS;
    __syncthreads();
    if (fast) {
        unsigned long long hp[8];
#pragma unroll
        for (int k = 0; k < 8; k++) hp[k] = 0ull;
#pragma unroll 2
        for (int t = 0; t < CHUNK; t++) {
            const float* row = sd[t];
            float4 d0 = *(const float4*)&row[0];
            float4 d1 = *(const float4*)&row[4];
            float a = dtb;
            a = fmaf(wdt[0], d0.x, a); a = fmaf(wdt[1], d0.y, a);
            a = fmaf(wdt[2], d0.z, a); a = fmaf(wdt[3], d0.w, a);
            a = fmaf(wdt[4], d1.x, a); a = fmaf(wdt[5], d1.y, a);
            a = fmaf(wdt[6], d1.z, a); a = fmaf(wdt[7], d1.w, a);
            float r, dt; dt_math(a, r, dt);
            float cB = dt * unpack_sum(xc[(size_t)t * DI]);
            float r2 = r * r;
            unsigned long long wp[8], s2 = pkf2(r2, r2);
            wp[0] = pkf2(r, r2);
#pragma unroll
            for (int k = 1; k < 8; k++) MULX2(wp[k], wp[k-1], s2);
            unsigned long long cBp = pkf2(cB, cB);
            const unsigned long long* Bp = (const unsigned long long*)&row[8];
#pragma unroll
            for (int k = 0; k < 8; k++) {
                unsigned long long t1;
                MULX2(t1, cBp, Bp[k]);
                FMAX2(hp[k], wp[k], hp[k], t1);
            }
            rP *= r;
        }
        float pw[NS];
        mkpow(rP, pw);
#pragma unroll
        for (int k = 0; k < 8; k++) {
            float hlo, hhi;
            upkf2(hp[k], hlo, hhi);
            g_hend[(base + 2*k)     * DI + d] = hlo;
            g_hend[(base + 2*k + 1) * DI + d] = hhi;
            g_P[(base + 2*k)     * DI + d] = pw[2*k];
            g_P[(base + 2*k + 1) * DI + d] = pw[2*k + 1];
        }
    } else {
        float h[NS];
#pragma unroll
        for (int n = 0; n < NS; n++) h[n] = 0.f;
        for (int t = 0; t < CHUNK; t++) {
            const float* row = sd[t];
            float a = dtb;
#pragma unroll
            for (int i = 0; i < DTR; i++) a = fmaf(wdt[i], row[i], a);
            float r, dt; dt_math(a, r, dt);
            float cB = dt * unpack_sum(xc[(size_t)t * DI]);
            S += dt;
#pragma unroll
            for (int n = 0; n < NS; n++)
                h[n] = fmaf(__expf(dt * Ad[n]), h[n], cB * row[8 + n]);
        }
#pragma unroll
        for (int n = 0; n < NS; n++) {
            g_hend[(base + n) * DI + d] = h[n];
            g_P[(base + n) * DI + d]    = __expf(Ad[n] * S);
        }
    }
}

// ------------------------- scan pass 2 --------------------------------------
__global__ void k_scan2() {
    int d = threadIdx.x;
    int n   = blockIdx.x & 15;
    int b   = (blockIdx.x >> 4) & 3;
    int dir = blockIdx.x >> 6;
    float hs = 0.f;
    for (int ch = 0; ch < NCH; ch++) {
        int idx = (((dir * NCH + ch) * BB + b) * NS + n) * DI + d;
        g_hinit[idx] = hs;
        hs = fmaf(g_P[idx], hs, g_hend[idx]);
    }
}

// ------------------------- scan pass 3 (packed f32x2 fast path) -------------
__global__ void k_scan3(const float* __restrict__ Alog_f, const float* __restrict__ Dsk_f,
                        const float* __restrict__ Alog_b, const float* __restrict__ Dsk_b,
                        const float* __restrict__ dtw_f, const float* __restrict__ dtb_f,
                        const float* __restrict__ dtw_b, const float* __restrict__ dtb_b) {
    int ch = blockIdx.x, b = blockIdx.y, dir = blockIdx.z, d = threadIdx.x;
    const float* Alog = dir ? Alog_b : Alog_f;
    const float* dtw  = dir ? dtw_b : dtw_f;
    float dtb = (dir ? dtb_b : dtb_f)[d];
    float Dd  = (dir ? Dsk_b : Dsk_f)[d];
    __shared__ __align__(16) float sd[CHUNK][40];
    int t0 = ch * CHUNK;
    const float* gsrc = g_dbl[dir] + (size_t)(b * LL + t0) * NDBL;
    for (int i = threadIdx.x; i < CHUNK * 10; i += 256) {
        int t = i / 10, q = i - t * 10;
        *((float4*)&sd[t][q * 4]) = *((const float4*)&gsrc[t * NDBL + q * 4]);
    }
    float Ad[NS], wdt[DTR];
    bool fast = true;
#pragma unroll
    for (int n = 0; n < NS; n++) {
        Ad[n] = -__expf(Alog[d * NS + n]);
        fast = fast && (fabsf(Ad[n] + (float)(n + 1)) <= 1e-5f * (n + 1));
    }
#pragma unroll
    for (int i = 0; i < DTR; i++) wdt[i] = dtw[d * DTR + i];
    int base = ((dir * NCH + ch) * BB + b) * NS;
    const uint32_t* xc = g_xc32[dir] + (size_t)(b * LL + t0) * DI + d;
    const float* xzz = g_xz + (size_t)b * LL * 512 + DI + d;   // pre-gated silu(z)
    float* yout = g_ydir[dir] + (size_t)b * LL * DI + d;
    __syncthreads();
    if (fast) {
        unsigned long long hp[8];
#pragma unroll
        for (int k = 0; k < 8; k++)
            hp[k] = pkf2(g_hinit[(base + 2*k) * DI + d],
                         g_hinit[(base + 2*k + 1) * DI + d]);
#pragma unroll 2
        for (int t = 0; t < CHUNK; t++) {
            const float* row = sd[t];
            float4 d0 = *(const float4*)&row[0];
            float4 d1 = *(const float4*)&row[4];
            float a = dtb;
            a = fmaf(wdt[0], d0.x, a); a = fmaf(wdt[1], d0.y, a);
            a = fmaf(wdt[2], d0.z, a); a = fmaf(wdt[3], d0.w, a);
            a = fmaf(wdt[4], d1.x, a); a = fmaf(wdt[5], d1.y, a);
            a = fmaf(wdt[6], d1.z, a); a = fmaf(wdt[7], d1.w, a);
            float r, dt; dt_math(a, r, dt);
            float xv = unpack_sum(xc[(size_t)t * DI]);
            float cB = dt * xv;
            float r2 = r * r;
            unsigned long long wp[8], s2 = pkf2(r2, r2);
            wp[0] = pkf2(r, r2);
#pragma unroll
            for (int k = 1; k < 8; k++) MULX2(wp[k], wp[k-1], s2);
            unsigned long long cBp = pkf2(cB, cB);
            const unsigned long long* Bp = (const unsigned long long*)&row[8];
            const unsigned long long* Cp = (const unsigned long long*)&row[24];
            unsigned long long yp = 0ull;
#pragma unroll
            for (int k = 0; k < 8; k++) {
                unsigned long long t1;
                MULX2(t1, cBp, Bp[k]);
                FMAX2(hp[k], wp[k], hp[k], t1);
                FMAX2(yp, hp[k], Cp[k], yp);
            }
            float ylo, yhi;
            upkf2(yp, ylo, yhi);
            float y = ylo + yhi;
            int torig = dir ? (LL - 1 - (t0 + t)) : (t0 + t);
            float zg = xzz[(size_t)torig * 512];
            yout[(size_t)torig * DI] = (y + xv * Dd) * zg;
        }
    } else {
        float h[NS];
#pragma unroll
        for (int n = 0; n < NS; n++) h[n] = g_hinit[(base + n) * DI + d];
        for (int t = 0; t < CHUNK; t++) {
            const float* row = sd[t];
            float a = dtb;
#pragma unroll
            for (int i = 0; i < DTR; i++) a = fmaf(wdt[i], row[i], a);
            float r, dt; dt_math(a, r, dt);
            float xv = unpack_sum(xc[(size_t)t * DI]);
            float cB = dt * xv;
            float y = 0.f;
#pragma unroll
            for (int n = 0; n < NS; n++) {
                h[n] = fmaf(__expf(dt * Ad[n]), h[n], cB * row[8 + n]);
                y = fmaf(h[n], row[24 + n], y);
            }
            int torig = dir ? (LL - 1 - (t0 + t)) : (t0 + t);
            float zg = xzz[(size_t)torig * 512];
            yout[(size_t)torig * DI] = (y + xv * Dd) * zg;
        }
    }
}

// ------------------------- launch ------------------------------------------
extern "C" void kernel_launch(void* const* d_in, const int* in_sizes, int n_in,
                              void* d_out, int out_size) {
    const float* x        = (const float*)d_in[0];
    const float* ln1_w    = (const float*)d_in[1];
    const float* ln1_b    = (const float*)d_in[2];
    const float* ln2_w    = (const float*)d_in[3];
    const float* ln2_b    = (const float*)d_in[4];
    const float* in_proj  = (const float*)d_in[5];
    const float* out_proj = (const float*)d_in[6];
    const float* conv_w_f = (const float*)d_in[7];
    const float* conv_b_f = (const float*)d_in[8];
    const float* xproj_f  = (const float*)d_in[9];
    const float* dtw_f    = (const float*)d_in[10];
    const float* dtb_f    = (const float*)d_in[11];
    const float* Alog_f   = (const float*)d_in[12];
    const float* D_f      = (const float*)d_in[13];
    const float* conv_w_b = (const float*)d_in[14];
    const float* conv_b_b = (const float*)d_in[15];
    const float* xproj_b  = (const float*)d_in[16];
    const float* dtw_b    = (const float*)d_in[17];
    const float* dtb_b    = (const float*)d_in[18];
    const float* Alog_b   = (const float*)d_in[19];
    const float* D_b      = (const float*)d_in[20];
    float* out = (float*)d_out;

    static bool attr_done = false;
    if (!attr_done) {
        cudaFuncSetAttribute(gemm_out, cudaFuncAttributeMaxDynamicSharedMemorySize, OUT_SMEM);
        cudaFuncSetAttribute(gemm_in_ln, cudaFuncAttributeMaxDynamicSharedMemorySize, IN_SMEM);
        attr_done = true;
    }

    float *p_xz, *p_dbl;
    cudaGetSymbolAddress((void**)&p_xz,  g_xz);
    cudaGetSymbolAddress((void**)&p_dbl, g_dbl);

    // 0. weight bf16 splits
    int wtot = 512 * 128 + 128 * 256 + 2 * 64 * 256;
    k_wconv<<<(wtot + 255) / 256, 256>>>(in_proj, out_proj, xproj_f, xproj_b);

    // 1. in_proj with fused LN1 (z half silu-gated): -> g_xz
    gemm_in_ln<<<dim3(MTOK / 128, 4), 256, IN_SMEM>>>(x, ln1_w, ln1_b, p_xz);

    // 2. conv + silu + packed split, both dirs
    k_conv2<<<dim3(LL / 16, BB), 256>>>(conv_w_f, conv_b_f, conv_w_b, conv_b_b);

    // 3. x_proj, both dirs in ONE launch
    gemm_xp<<<dim3(MTOK / 128, 2), 256>>>(p_dbl);

    // 4-6. chunked selective scan (f32x2-packed hot loops)
    k_scan1<<<dim3(NCH, BB, 2), 256>>>(Alog_f, Alog_b, dtw_f, dtb_f, dtw_b, dtb_b);
    k_scan2<<<2 * BB * NS, 256>>>();
    k_scan3<<<dim3(NCH, BB, 2), 256>>>(Alog_f, D_f, Alog_b, D_b,
                                       dtw_f, dtb_f, dtw_b, dtb_b);

    // 7. out_proj + residual + LN2 -> final output
    gemm_out<<<dim3(MTOK / 128, 1), 256, OUT_SMEM>>>(x, ln2_w, ln2_b, out);
}